// round 1
// baseline (speedup 1.0000x reference)
#include <cuda_runtime.h>
#include <cuda_bf16.h>
#include <cstdint>

// Problem constants
#define BB 16
#define PP 8192
#define NN (BB*PP)          // 131072
#define FEAT 6
#define MM 128              // MAX_TOKENS
#define DD 768              // TOKEN_DIM
#define KK 16               // kNN
#define GG (BB*MM)          // 2048 groups
#define RR (GG*KK)          // 32768 gathered rows

// ---------------- scratch (static device globals; no allocs) ----------------
__device__ float4 g_pts[NN];            // packed xyzt
__device__ float4 g_cent[GG];           // centroids
__device__ int    g_knn[RR];            // knn indices (within batch)
__device__ float  g_h1[(size_t)RR*256];
__device__ float  g_h2[(size_t)RR*512];
__device__ float  g_h3[(size_t)RR*768];
__device__ float  g_emb[(size_t)RR*768];
__device__ float  g_pool[(size_t)GG*768];
__device__ float  g_t1[(size_t)GG*768];

// ---------------- kernel 0: pack coordinates[:,1:5] into float4 -------------
__global__ void pack_kernel(const float* __restrict__ coords) {
    int i = blockIdx.x * 256 + threadIdx.x;
    if (i < NN) {
        const float* c = coords + (size_t)i * 5;
        g_pts[i] = make_float4(c[1], c[2], c[3], c[4]);
    }
}

// ---------------- kernel 1: farthest point sampling (one block/batch) -------
__global__ __launch_bounds__(1024) void fps_kernel() {
    int b = blockIdx.x;
    int tid = threadIdx.x;
    const float4* pb = g_pts + (size_t)b * PP;

    float4 pt[8];
    float dmin[8];
#pragma unroll
    for (int t = 0; t < 8; ++t) {
        pt[t] = pb[tid + t * 1024];
        dmin[t] = 1e30f;
    }

    __shared__ float4 s_last;
    __shared__ float s_v[32];
    __shared__ int   s_i[32];

    if (tid == 0) {
        s_last = pb[0];
        g_cent[b * MM + 0] = pb[0];
    }
    __syncthreads();

    for (int it = 1; it < MM; ++it) {
        float4 c = s_last;
        float bv = -1.0f; int bi = 0;
#pragma unroll
        for (int t = 0; t < 8; ++t) {
            float dx = pt[t].x - c.x, dy = pt[t].y - c.y;
            float dz = pt[t].z - c.z, dw = pt[t].w - c.w;
            float d = dx*dx + dy*dy + dz*dz + dw*dw;
            dmin[t] = fminf(dmin[t], d);
            int gi = tid + t * 1024;
            if (dmin[t] > bv) { bv = dmin[t]; bi = gi; }   // gi ascending -> first-max
        }
        // warp argmax (tie -> smaller index)
#pragma unroll
        for (int off = 16; off; off >>= 1) {
            float ov = __shfl_down_sync(0xffffffffu, bv, off);
            int   oi = __shfl_down_sync(0xffffffffu, bi, off);
            if (ov > bv || (ov == bv && oi < bi)) { bv = ov; bi = oi; }
        }
        if ((tid & 31) == 0) { s_v[tid >> 5] = bv; s_i[tid >> 5] = bi; }
        __syncthreads();
        if (tid < 32) {
            bv = s_v[tid]; bi = s_i[tid];
#pragma unroll
            for (int off = 16; off; off >>= 1) {
                float ov = __shfl_down_sync(0xffffffffu, bv, off);
                int   oi = __shfl_down_sync(0xffffffffu, bi, off);
                if (ov > bv || (ov == bv && oi < bi)) { bv = ov; bi = oi; }
            }
            if (tid == 0) {
                float4 np = pb[bi];
                s_last = np;
                g_cent[b * MM + it] = np;
            }
        }
        __syncthreads();
    }
}

// ---------------- kernel 2: kNN (one warp per (b,m), top-16 smallest) -------
__global__ __launch_bounds__(256) void knn_kernel() {
    __shared__ float sv[8][512];
    __shared__ int   si[8][512];
    int w = threadIdx.x >> 5;
    int lane = threadIdx.x & 31;
    int g = blockIdx.x * 8 + w;          // < 2048
    int b = g >> 7;
    const float4* pb = g_pts + (size_t)b * PP;
    float4 c = g_cent[g];

    float bv[16]; int bi[16];
#pragma unroll
    for (int i = 0; i < 16; ++i) { bv[i] = 1e30f; bi[i] = 0; }
    float worst = 1e30f; int wpos = 0;

    for (int p = lane; p < PP; p += 32) {
        float4 q = __ldg(&pb[p]);
        float dx = q.x - c.x, dy = q.y - c.y, dz = q.z - c.z, dw = q.w - c.w;
        float d = dx*dx + dy*dy + dz*dz + dw*dw;
        if (d < worst) {
#pragma unroll
            for (int i = 0; i < 16; ++i) if (i == wpos) { bv[i] = d; bi[i] = p; }
            worst = -1.0f;
#pragma unroll
            for (int i = 0; i < 16; ++i) if (bv[i] > worst) { worst = bv[i]; wpos = i; }
        }
    }
#pragma unroll
    for (int i = 0; i < 16; ++i) { sv[w][lane * 16 + i] = bv[i]; si[w][lane * 16 + i] = bi[i]; }
    __syncwarp();

    for (int r = 0; r < 16; ++r) {
        float mv = 1e30f; int me = 0;
#pragma unroll
        for (int j = 0; j < 16; ++j) {
            int e = j * 32 + lane;
            float v = sv[w][e];
            if (v < mv) { mv = v; me = e; }
        }
#pragma unroll
        for (int off = 16; off; off >>= 1) {
            float ov = __shfl_xor_sync(0xffffffffu, mv, off);
            int   oe = __shfl_xor_sync(0xffffffffu, me, off);
            if (ov < mv || (ov == mv && oe < me)) { mv = ov; me = oe; }
        }
        if (lane == 0) { g_knn[g * 16 + r] = si[w][me]; sv[w][me] = 1e30f; }
        __syncwarp();
    }
}

// ---------------- kernel 3: gather + layer1 (6 -> 256, relu) ----------------
__global__ __launch_bounds__(256) void layer1_kernel(const float* __restrict__ feats,
                                                     const float* __restrict__ W1,
                                                     const float* __restrict__ b1) {
    int j = threadIdx.x;       // col 0..255
    int r0 = blockIdx.x * 8;
    __shared__ float sf[8][6];
    if (threadIdx.x < 48) {
        int rr = threadIdx.x / 6, f = threadIdx.x % 6;
        int r = r0 + rr;
        int g = r >> 4;        // /K
        int b = g >> 7;        // /M
        int p = g_knn[r];
        sf[rr][f] = feats[((size_t)b * PP + p) * 6 + f];
    }
    float w[6];
#pragma unroll
    for (int f = 0; f < 6; ++f) w[f] = W1[f * 256 + j];
    float bj = b1[j];
    __syncthreads();
#pragma unroll
    for (int rr = 0; rr < 8; ++rr) {
        float acc = bj;
#pragma unroll
        for (int f = 0; f < 6; ++f) acc += sf[rr][f] * w[f];
        g_h1[(size_t)(r0 + rr) * 256 + j] = fmaxf(acc, 0.0f);
    }
}

// ---------------- generic fp32 SGEMM: C = [relu](A @ W + bias) --------------
// A: Mrows x Kd (row-major), W: Kd x Nd (row-major). BM=BN=128, BK=16, 8x8/thr.
template<bool RELU>
__global__ __launch_bounds__(256) void sgemm_kernel(const float* __restrict__ A,
                                                    const float* __restrict__ W,
                                                    const float* __restrict__ bias,
                                                    float* __restrict__ C,
                                                    int Kd, int Nd) {
    constexpr int BM = 128, BN = 128, BK = 16, TM = 8, TN = 8;
    __shared__ float As[BK][BM];
    __shared__ float Bs[BK][BN];
    int tid = threadIdx.x;
    int bm = blockIdx.y * BM;
    int bn = blockIdx.x * BN;
    int tr = (tid / 16) * TM;
    int tc = (tid % 16) * TN;
    int a_r = tid >> 1, a_c = (tid & 1) * 8;
    int w_r = tid >> 4, w_c = (tid & 15) * 8;
    const float* Ag = A + (size_t)(bm + a_r) * Kd + a_c;
    const float* Wg = W + (size_t)w_r * Nd + bn + w_c;

    float acc[TM][TN];
#pragma unroll
    for (int i = 0; i < TM; ++i)
#pragma unroll
        for (int j = 0; j < TN; ++j) acc[i][j] = 0.0f;

    for (int k0 = 0; k0 < Kd; k0 += BK) {
        float4 a0 = *(const float4*)(Ag + k0);
        float4 a1 = *(const float4*)(Ag + k0 + 4);
        As[a_c + 0][a_r] = a0.x; As[a_c + 1][a_r] = a0.y;
        As[a_c + 2][a_r] = a0.z; As[a_c + 3][a_r] = a0.w;
        As[a_c + 4][a_r] = a1.x; As[a_c + 5][a_r] = a1.y;
        As[a_c + 6][a_r] = a1.z; As[a_c + 7][a_r] = a1.w;
        const float* wg = Wg + (size_t)k0 * Nd;
        float4 w0 = *(const float4*)(wg);
        float4 w1 = *(const float4*)(wg + 4);
        *(float4*)&Bs[w_r][w_c] = w0;
        *(float4*)&Bs[w_r][w_c + 4] = w1;
        __syncthreads();
#pragma unroll
        for (int kk = 0; kk < BK; ++kk) {
            float ra[TM], rb[TN];
#pragma unroll
            for (int i = 0; i < TM; ++i) ra[i] = As[kk][tr + i];
#pragma unroll
            for (int j = 0; j < TN; ++j) rb[j] = Bs[kk][tc + j];
#pragma unroll
            for (int i = 0; i < TM; ++i)
#pragma unroll
                for (int j = 0; j < TN; ++j) acc[i][j] += ra[i] * rb[j];
        }
        __syncthreads();
    }
#pragma unroll
    for (int i = 0; i < TM; ++i) {
        size_t row = (size_t)(bm + tr + i);
#pragma unroll
        for (int j = 0; j < TN; ++j) {
            float v = acc[i][j] + bias[bn + tc + j];
            if (RELU) v = fmaxf(v, 0.0f);
            C[row * Nd + bn + tc + j] = v;
        }
    }
}

// ---------------- kernel: max pool over K=16 --------------------------------
__global__ void pool_kernel() {
    int i = blockIdx.x * 256 + threadIdx.x;    // over GG*768
    if (i >= GG * 768) return;
    int g = i / 768, j = i % 768;
    const float* e = g_emb + ((size_t)g * 16) * 768 + j;
    float m = e[0];
#pragma unroll
    for (int k = 1; k < 16; ++k) m = fmaxf(m, e[(size_t)k * 768]);
    g_pool[i] = m;
}

// ---------------- epilogue: centroids + masks + tail ------------------------
__global__ void epilogue_kernel(float* __restrict__ out, int extra) {
    // index space i over [0, extra) appended after tokens (GG*768 floats)
    int i = blockIdx.x * 256 + threadIdx.x;
    if (i >= extra) return;
    const int T0 = GG * 768;
    float v;
    if (i < GG * 4) {
        const float4 c = g_cent[i >> 2];
        int comp = i & 3;
        v = (comp == 0) ? c.x : (comp == 1) ? c.y : (comp == 2) ? c.z : c.w;
    } else if (i < GG * 4 + GG) {
        v = 1.0f;          // masks: all valid
    } else {
        v = 0.0f;          // unknown tail: zero-fill
    }
    out[T0 + i] = v;
}

// ---------------- host launcher ---------------------------------------------
static float* symf(const void* s) { void* p = nullptr; cudaGetSymbolAddress(&p, s); return (float*)p; }

extern "C" void kernel_launch(void* const* d_in, const int* in_sizes, int n_in,
                              void* d_out, int out_size) {
    const float* coords = (const float*)d_in[0];
    const float* feats  = (const float*)d_in[1];
    const float* W1 = (const float*)d_in[2];
    const float* b1 = (const float*)d_in[3];
    const float* W2 = (const float*)d_in[4];
    const float* b2 = (const float*)d_in[5];
    const float* W3 = (const float*)d_in[6];
    const float* b3 = (const float*)d_in[7];
    const float* W4 = (const float*)d_in[8];
    const float* b4 = (const float*)d_in[9];
    const float* Wa1 = (const float*)d_in[10];
    const float* ba1 = (const float*)d_in[11];
    const float* Wa2 = (const float*)d_in[12];
    const float* ba2 = (const float*)d_in[13];
    float* out = (float*)d_out;

    float* h1  = symf(g_h1);
    float* h2  = symf(g_h2);
    float* h3  = symf(g_h3);
    float* emb = symf(g_emb);
    float* pool = symf(g_pool);
    float* t1  = symf(g_t1);

    pack_kernel<<<(NN + 255) / 256, 256>>>(coords);
    fps_kernel<<<BB, 1024>>>();
    knn_kernel<<<GG / 8, 256>>>();
    layer1_kernel<<<RR / 8, 256>>>(feats, W1, b1);

    // h2 = relu(h1 @ W2 + b2)   [32768 x 512]
    sgemm_kernel<true ><<<dim3(512 / 128, RR / 128), 256>>>(h1, W2, b2, h2, 256, 512);
    // h3 = relu(h2 @ W3 + b3)   [32768 x 768]
    sgemm_kernel<true ><<<dim3(768 / 128, RR / 128), 256>>>(h2, W3, b3, h3, 512, 768);
    // emb = h3 @ W4 + b4        [32768 x 768]
    sgemm_kernel<false><<<dim3(768 / 128, RR / 128), 256>>>(h3, W4, b4, emb, 768, 768);

    pool_kernel<<<(GG * 768 + 255) / 256, 256>>>();

    // t1 = relu(pool @ Wa1 + ba1)   [2048 x 768]
    sgemm_kernel<true ><<<dim3(768 / 128, GG / 128), 256>>>(pool, Wa1, ba1, t1, 768, 768);
    // tokens = t1 @ Wa2 + ba2  -> directly into d_out
    sgemm_kernel<false><<<dim3(768 / 128, GG / 128), 256>>>(t1, Wa2, ba2, out, 768, 768);

    int extra = out_size - GG * 768;
    if (extra > 0) {
        epilogue_kernel<<<(extra + 255) / 256, 256>>>(out, extra);
    }
}

// round 5
// speedup vs baseline: 1.4167x; 1.4167x over previous
#include <cuda_runtime.h>
#include <cuda_bf16.h>
#include <cstdint>

// Problem constants
#define BB 16
#define PP 8192
#define NN (BB*PP)          // 131072
#define FEAT 6
#define MM 128              // MAX_TOKENS
#define DD 768              // TOKEN_DIM
#define KK 16               // kNN
#define GG (BB*MM)          // 2048 groups
#define RR (GG*KK)          // 32768 gathered rows

typedef __nv_bfloat16 bf16;

// ---------------- scratch (static device globals; no allocs) ----------------
__device__ float4 g_pts[NN];
__device__ float4 g_cent[GG];
__device__ int    g_knn[RR];
__device__ bf16   g_h1h[(size_t)RR*256],  g_h1l[(size_t)RR*256];
__device__ bf16   g_h2h[(size_t)RR*512],  g_h2l[(size_t)RR*512];
__device__ bf16   g_h3h[(size_t)RR*768],  g_h3l[(size_t)RR*768];
__device__ float  g_emb[(size_t)RR*768];
__device__ bf16   g_plh[(size_t)GG*768],  g_pll[(size_t)GG*768];
__device__ bf16   g_t1h[(size_t)GG*768],  g_t1l[(size_t)GG*768];
// transposed weights Wt[N,K] split hi/lo
__device__ bf16   g_w2h[512*256],  g_w2l[512*256];
__device__ bf16   g_w3h[768*512],  g_w3l[768*512];
__device__ bf16   g_w4h[768*768],  g_w4l[768*768];
__device__ bf16   g_wa1h[768*768], g_wa1l[768*768];
__device__ bf16   g_wa2h[768*768], g_wa2l[768*768];

__device__ __forceinline__ void split_bf16(float v, bf16& hi, bf16& lo) {
    hi = __float2bfloat16_rn(v);
    lo = __float2bfloat16_rn(v - __bfloat162float(hi));
}

__device__ __forceinline__ uint32_t smem_u32(const void* p) {
    uint32_t a;
    asm("{ .reg .u64 t; cvta.to.shared.u64 t, %1; cvt.u32.u64 %0, t; }" : "=r"(a) : "l"(p));
    return a;
}
__device__ __forceinline__ void cpasync16(uint32_t dst, const void* src) {
    asm volatile("cp.async.cg.shared.global [%0], [%1], 16;"
                 :: "r"(dst), "l"(__cvta_generic_to_global(src)));
}
#define CP_COMMIT() asm volatile("cp.async.commit_group;" ::: "memory")
#define CP_WAIT(n)  asm volatile("cp.async.wait_group %0;" :: "n"(n) : "memory")

__device__ __forceinline__ void ldmx4(uint32_t* r, uint32_t addr) {
    asm volatile("ldmatrix.sync.aligned.m8n8.x4.shared.b16 {%0,%1,%2,%3}, [%4];"
                 : "=r"(r[0]), "=r"(r[1]), "=r"(r[2]), "=r"(r[3]) : "r"(addr));
}
__device__ __forceinline__ void mma16816(float* d, const uint32_t* a, const uint32_t* b) {
    asm volatile("mma.sync.aligned.m16n8k16.row.col.f32.bf16.bf16.f32 "
                 "{%0,%1,%2,%3}, {%4,%5,%6,%7}, {%8,%9}, {%0,%1,%2,%3};"
                 : "+f"(d[0]), "+f"(d[1]), "+f"(d[2]), "+f"(d[3])
                 : "r"(a[0]), "r"(a[1]), "r"(a[2]), "r"(a[3]), "r"(b[0]), "r"(b[1]));
}

// ---------------- kernel 0: pack coordinates[:,1:5] into float4 -------------
__global__ void pack_kernel(const float* __restrict__ coords) {
    int i = blockIdx.x * 256 + threadIdx.x;
    if (i < NN) {
        const float* c = coords + (size_t)i * 5;
        g_pts[i] = make_float4(c[1], c[2], c[3], c[4]);
    }
}

// ---------------- kernel 1: farthest point sampling (one block/batch) -------
__global__ __launch_bounds__(1024) void fps_kernel() {
    int b = blockIdx.x;
    int tid = threadIdx.x;
    const float4* pb = g_pts + (size_t)b * PP;

    float4 pt[8];
    float dmin[8];
#pragma unroll
    for (int t = 0; t < 8; ++t) { pt[t] = pb[tid + t * 1024]; dmin[t] = 1e30f; }

    __shared__ float4 s_last;
    __shared__ float s_v[32];
    __shared__ int   s_i[32];

    if (tid == 0) { s_last = pb[0]; g_cent[b * MM + 0] = pb[0]; }
    __syncthreads();

    for (int it = 1; it < MM; ++it) {
        float4 c = s_last;
        float bv = -1.0f; int bi = 0;
#pragma unroll
        for (int t = 0; t < 8; ++t) {
            float dx = pt[t].x - c.x, dy = pt[t].y - c.y;
            float dz = pt[t].z - c.z, dw = pt[t].w - c.w;
            float d = dx*dx + dy*dy + dz*dz + dw*dw;
            dmin[t] = fminf(dmin[t], d);
            int gi = tid + t * 1024;
            if (dmin[t] > bv) { bv = dmin[t]; bi = gi; }
        }
#pragma unroll
        for (int off = 16; off; off >>= 1) {
            float ov = __shfl_down_sync(0xffffffffu, bv, off);
            int   oi = __shfl_down_sync(0xffffffffu, bi, off);
            if (ov > bv || (ov == bv && oi < bi)) { bv = ov; bi = oi; }
        }
        if ((tid & 31) == 0) { s_v[tid >> 5] = bv; s_i[tid >> 5] = bi; }
        __syncthreads();
        if (tid < 32) {
            bv = s_v[tid]; bi = s_i[tid];
#pragma unroll
            for (int off = 16; off; off >>= 1) {
                float ov = __shfl_down_sync(0xffffffffu, bv, off);
                int   oi = __shfl_down_sync(0xffffffffu, bi, off);
                if (ov > bv || (ov == bv && oi < bi)) { bv = ov; bi = oi; }
            }
            if (tid == 0) {
                float4 np = pb[bi];
                s_last = np;
                g_cent[b * MM + it] = np;
            }
        }
        __syncthreads();
    }
}

// ---------------- kernel 2: kNN (one warp per (b,m), top-16 smallest) -------
__global__ __launch_bounds__(256) void knn_kernel() {
    __shared__ float sv[8][512];
    __shared__ int   si[8][512];
    int w = threadIdx.x >> 5;
    int lane = threadIdx.x & 31;
    int g = blockIdx.x * 8 + w;
    int b = g >> 7;
    const float4* pb = g_pts + (size_t)b * PP;
    float4 c = g_cent[g];

    float bv[16]; int bi[16];
#pragma unroll
    for (int i = 0; i < 16; ++i) { bv[i] = 1e30f; bi[i] = 0; }
    float worst = 1e30f; int wpos = 0;

    for (int p = lane; p < PP; p += 32) {
        float4 q = __ldg(&pb[p]);
        float dx = q.x - c.x, dy = q.y - c.y, dz = q.z - c.z, dw = q.w - c.w;
        float d = dx*dx + dy*dy + dz*dz + dw*dw;
        if (d < worst) {
#pragma unroll
            for (int i = 0; i < 16; ++i) if (i == wpos) { bv[i] = d; bi[i] = p; }
            worst = -1.0f;
#pragma unroll
            for (int i = 0; i < 16; ++i) if (bv[i] > worst) { worst = bv[i]; wpos = i; }
        }
    }
#pragma unroll
    for (int i = 0; i < 16; ++i) { sv[w][lane * 16 + i] = bv[i]; si[w][lane * 16 + i] = bi[i]; }
    __syncwarp();

    for (int r = 0; r < 16; ++r) {
        float mv = 1e30f; int me = 0;
#pragma unroll
        for (int j = 0; j < 16; ++j) {
            int e = j * 32 + lane;
            float v = sv[w][e];
            if (v < mv) { mv = v; me = e; }
        }
#pragma unroll
        for (int off = 16; off; off >>= 1) {
            float ov = __shfl_xor_sync(0xffffffffu, mv, off);
            int   oe = __shfl_xor_sync(0xffffffffu, me, off);
            if (ov < mv || (ov == mv && oe < me)) { mv = ov; me = oe; }
        }
        if (lane == 0) { g_knn[g * 16 + r] = si[w][me]; sv[w][me] = 1e30f; }
        __syncwarp();
    }
}

// ---------------- kernel 3: gather + layer1 (6 -> 256, relu), split out -----
__global__ __launch_bounds__(256) void layer1_kernel(const float* __restrict__ feats,
                                                     const float* __restrict__ W1,
                                                     const float* __restrict__ b1) {
    int j = threadIdx.x;
    int r0 = blockIdx.x * 8;
    __shared__ float sf[8][6];
    if (threadIdx.x < 48) {
        int rr = threadIdx.x / 6, f = threadIdx.x % 6;
        int r = r0 + rr;
        int g = r >> 4;
        int b = g >> 7;
        int p = g_knn[r];
        sf[rr][f] = feats[((size_t)b * PP + p) * 6 + f];
    }
    float w[6];
#pragma unroll
    for (int f = 0; f < 6; ++f) w[f] = W1[f * 256 + j];
    float bj = b1[j];
    __syncthreads();
#pragma unroll
    for (int rr = 0; rr < 8; ++rr) {
        float acc = bj;
#pragma unroll
        for (int f = 0; f < 6; ++f) acc += sf[rr][f] * w[f];
        float v = fmaxf(acc, 0.0f);
        bf16 hi, lo; split_bf16(v, hi, lo);
        size_t o = (size_t)(r0 + rr) * 256 + j;
        g_h1h[o] = hi; g_h1l[o] = lo;
    }
}

// ---------------- weight conversion: W[K,N] fp32 -> Wt[N,K] bf16 hi/lo ------
__global__ void convw_kernel(const float* __restrict__ W, int Kd, int Nd,
                             bf16* __restrict__ Wh, bf16* __restrict__ Wl) {
    int i = blockIdx.x * 256 + threadIdx.x;
    if (i >= Kd * Nd) return;
    int k = i / Nd, n = i % Nd;
    bf16 hi, lo; split_bf16(W[i], hi, lo);
    Wh[(size_t)n * Kd + k] = hi;
    Wl[(size_t)n * Kd + k] = lo;
}

// ---------------- HMMA bf16 split GEMM --------------------------------------
// C[M,N] = act(A @ W + bias); A hi/lo [Mrows,K] bf16 row-major,
// W transposed hi/lo [N,K]. CTA tile 128x128, BK=32, 8 warps (warp 32m x 64n).
// K' = 3K phases: (Ahi,Whi), (Ahi,Wlo), (Alo,Whi). fp32 accum in registers.
#define ROWB 80          // padded smem row stride in bytes (32 bf16 = 64B data)
#define STG  10240       // 128 rows * 80 B
template<bool RELU, bool WF32, bool WSPLIT>
__global__ __launch_bounds__(256) void gemm_kernel(
    const bf16* __restrict__ Ahi, const bf16* __restrict__ Alo,
    const bf16* __restrict__ Bhi, const bf16* __restrict__ Blo,
    const float* __restrict__ bias,
    float* __restrict__ Cf, bf16* __restrict__ Chi, bf16* __restrict__ Clo,
    int Kd, int Nd)
{
    __shared__ __align__(16) char smem[2 * 2 * STG];   // [stage][A/B]
    uint32_t sb = smem_u32(smem);

    const int tid  = threadIdx.x;
    const int wid  = tid >> 5;
    const int lane = tid & 31;
    const int bm = blockIdx.y * 128;
    const int bn = blockIdx.x * 128;
    const int wm = (wid & 3) * 32;     // warp m offset
    const int wn = (wid >> 2) * 64;    // warp n offset

    const int kchunks = Kd >> 5;       // 32-wide chunks per phase
    const int C = 3 * kchunks;

    float acc[2][8][4];
#pragma unroll
    for (int i = 0; i < 2; ++i)
#pragma unroll
        for (int j = 0; j < 8; ++j)
#pragma unroll
            for (int q = 0; q < 4; ++q) acc[i][j][q] = 0.0f;

    // per-thread load mapping: row = tid/2, two 16B chunks at (tid&1)*32B
    const int lrow = tid >> 1;
    const int lofs = (tid & 1) * 16;   // element offset (16 bf16 = 32B)

    auto load_chunk = [&](int c, int s) {
        int phase = c / kchunks;
        int kk = c - phase * kchunks;
        const bf16* Ap = (phase < 2) ? Ahi : Alo;
        const bf16* Bp = (phase == 1) ? Blo : Bhi;
        const bf16* asrc = Ap + ((size_t)(bm + lrow)) * Kd + kk * 32 + lofs;
        const bf16* bsrc = Bp + ((size_t)(bn + lrow)) * Kd + kk * 32 + lofs;
        uint32_t ad = sb + s * 2 * STG + lrow * ROWB + lofs * 2;
        uint32_t bd = ad + STG;
        cpasync16(ad, asrc);       cpasync16(ad + 16, asrc + 8);
        cpasync16(bd, bsrc);       cpasync16(bd + 16, bsrc + 8);
        CP_COMMIT();
    };

    // ldmatrix lane addressing (constant per thread)
    const int a_r = lane & 15;                 // m within 16
    const int a_c = (lane >> 4) << 3;          // k 0/8
    const int b_r = ((lane >> 4) << 3) + (lane & 7);   // n within 16
    const int b_c = ((lane >> 3) & 1) << 3;            // k 0/8

    load_chunk(0, 0);

    for (int c = 0; c < C; ++c) {
        int s = c & 1;
        if (c + 1 < C) { load_chunk(c + 1, s ^ 1); CP_WAIT(1); }
        else           { CP_WAIT(0); }
        __syncthreads();

        uint32_t Ab = sb + s * 2 * STG;
        uint32_t Bb = Ab + STG;
#pragma unroll
        for (int k16 = 0; k16 < 2; ++k16) {
            int k0 = k16 * 16;
            uint32_t a[2][4];
#pragma unroll
            for (int mt = 0; mt < 2; ++mt)
                ldmx4(a[mt], Ab + (wm + mt * 16 + a_r) * ROWB + (k0 + a_c) * 2);
            uint32_t b[4][4];
#pragma unroll
            for (int nt = 0; nt < 4; ++nt)
                ldmx4(b[nt], Bb + (wn + nt * 16 + b_r) * ROWB + (k0 + b_c) * 2);
#pragma unroll
            for (int mt = 0; mt < 2; ++mt)
#pragma unroll
                for (int nt = 0; nt < 4; ++nt) {
                    mma16816(acc[mt][nt * 2 + 0], a[mt], &b[nt][0]);
                    mma16816(acc[mt][nt * 2 + 1], a[mt], &b[nt][2]);
                }
        }
        __syncthreads();
    }

    // epilogue
    const int r0 = lane >> 2;
    const int c0 = (lane & 3) * 2;
#pragma unroll
    for (int mt = 0; mt < 2; ++mt) {
#pragma unroll
        for (int nt8 = 0; nt8 < 8; ++nt8) {
            float* d = acc[mt][nt8];
            int gr = bm + wm + mt * 16 + r0;
            int gc = bn + wn + nt8 * 8 + c0;
#pragma unroll
            for (int q = 0; q < 4; ++q) {
                int rr = gr + (q >> 1) * 8;
                int cc = gc + (q & 1);
                float v = d[q] + __ldg(&bias[cc]);
                if (RELU) v = fmaxf(v, 0.0f);
                size_t o = (size_t)rr * Nd + cc;
                if (WF32) Cf[o] = v;
                if (WSPLIT) { bf16 hi, lo; split_bf16(v, hi, lo); Chi[o] = hi; Clo[o] = lo; }
            }
        }
    }
}

// ---------------- kernel: max pool over K=16, split output ------------------
__global__ void pool_kernel() {
    int i = blockIdx.x * 256 + threadIdx.x;
    if (i >= GG * 768) return;
    int g = i / 768, j = i % 768;
    const float* e = g_emb + ((size_t)g * 16) * 768 + j;
    float m = e[0];
#pragma unroll
    for (int k = 1; k < 16; ++k) m = fmaxf(m, e[(size_t)k * 768]);
    bf16 hi, lo; split_bf16(m, hi, lo);
    g_plh[i] = hi; g_pll[i] = lo;
}

// ---------------- epilogue: centroids + masks + tail ------------------------
__global__ void epilogue_kernel(float* __restrict__ out, int extra) {
    int i = blockIdx.x * 256 + threadIdx.x;
    if (i >= extra) return;
    const int T0 = GG * 768;
    float v;
    if (i < GG * 4) {
        const float4 c = g_cent[i >> 2];
        int comp = i & 3;
        v = (comp == 0) ? c.x : (comp == 1) ? c.y : (comp == 2) ? c.z : c.w;
    } else if (i < GG * 4 + GG) {
        v = 1.0f;
    } else {
        v = 0.0f;
    }
    out[T0 + i] = v;
}

// ---------------- host launcher ---------------------------------------------
template<typename T> static T* sym(const void* s) { void* p = nullptr; cudaGetSymbolAddress(&p, s); return (T*)p; }

extern "C" void kernel_launch(void* const* d_in, const int* in_sizes, int n_in,
                              void* d_out, int out_size) {
    const float* coords = (const float*)d_in[0];
    const float* feats  = (const float*)d_in[1];
    const float* W1 = (const float*)d_in[2];
    const float* b1 = (const float*)d_in[3];
    const float* W2 = (const float*)d_in[4];
    const float* b2 = (const float*)d_in[5];
    const float* W3 = (const float*)d_in[6];
    const float* b3 = (const float*)d_in[7];
    const float* W4 = (const float*)d_in[8];
    const float* b4 = (const float*)d_in[9];
    const float* Wa1 = (const float*)d_in[10];
    const float* ba1 = (const float*)d_in[11];
    const float* Wa2 = (const float*)d_in[12];
    const float* ba2 = (const float*)d_in[13];
    float* out = (float*)d_out;

    bf16 *h1h = sym<bf16>(g_h1h), *h1l = sym<bf16>(g_h1l);
    bf16 *h2h = sym<bf16>(g_h2h), *h2l = sym<bf16>(g_h2l);
    bf16 *h3h = sym<bf16>(g_h3h), *h3l = sym<bf16>(g_h3l);
    float *emb = sym<float>(g_emb);
    bf16 *plh = sym<bf16>(g_plh), *pll = sym<bf16>(g_pll);
    bf16 *t1h = sym<bf16>(g_t1h), *t1l = sym<bf16>(g_t1l);
    bf16 *w2h = sym<bf16>(g_w2h), *w2l = sym<bf16>(g_w2l);
    bf16 *w3h = sym<bf16>(g_w3h), *w3l = sym<bf16>(g_w3l);
    bf16 *w4h = sym<bf16>(g_w4h), *w4l = sym<bf16>(g_w4l);
    bf16 *wa1h = sym<bf16>(g_wa1h), *wa1l = sym<bf16>(g_wa1l);
    bf16 *wa2h = sym<bf16>(g_wa2h), *wa2l = sym<bf16>(g_wa2l);

    // geometry + weight conversion (independent, early)
    pack_kernel<<<(NN + 255) / 256, 256>>>(coords);
    convw_kernel<<<(256 * 512 + 255) / 256, 256>>>(W2, 256, 512, w2h, w2l);
    convw_kernel<<<(512 * 768 + 255) / 256, 256>>>(W3, 512, 768, w3h, w3l);
    convw_kernel<<<(768 * 768 + 255) / 256, 256>>>(W4, 768, 768, w4h, w4l);
    convw_kernel<<<(768 * 768 + 255) / 256, 256>>>(Wa1, 768, 768, wa1h, wa1l);
    convw_kernel<<<(768 * 768 + 255) / 256, 256>>>(Wa2, 768, 768, wa2h, wa2l);

    fps_kernel<<<BB, 1024>>>();
    knn_kernel<<<GG / 8, 256>>>();
    layer1_kernel<<<RR / 8, 256>>>(feats, W1, b1);

    // h2 = relu(h1 @ W2 + b2): [32768,256] x [256,512]
    gemm_kernel<true, false, true><<<dim3(512 / 128, RR / 128), 256>>>(
        h1h, h1l, w2h, w2l, b2, nullptr, h2h, h2l, 256, 512);
    // h3 = relu(h2 @ W3 + b3): [32768,512] x [512,768]
    gemm_kernel<true, false, true><<<dim3(768 / 128, RR / 128), 256>>>(
        h2h, h2l, w3h, w3l, b3, nullptr, h3h, h3l, 512, 768);
    // emb = h3 @ W4 + b4: [32768,768] x [768,768] -> fp32
    gemm_kernel<false, true, false><<<dim3(768 / 128, RR / 128), 256>>>(
        h3h, h3l, w4h, w4l, b4, emb, nullptr, nullptr, 768, 768);

    pool_kernel<<<(GG * 768 + 255) / 256, 256>>>();

    // t1 = relu(pool @ Wa1 + ba1): [2048,768] x [768,768]
    gemm_kernel<true, false, true><<<dim3(768 / 128, GG / 128), 256>>>(
        plh, pll, wa1h, wa1l, ba1, nullptr, t1h, t1l, 768, 768);
    // tokens = t1 @ Wa2 + ba2 -> d_out fp32
    gemm_kernel<false, true, false><<<dim3(768 / 128, GG / 128), 256>>>(
        t1h, t1l, wa2h, wa2l, ba2, out, nullptr, nullptr, 768, 768);

    int extra = out_size - GG * 768;
    if (extra > 0) {
        epilogue_kernel<<<(extra + 255) / 256, 256>>>(out, extra);
    }
}

// round 7
// speedup vs baseline: 1.4842x; 1.0477x over previous
#include <cuda_runtime.h>
#include <cuda_bf16.h>
#include <cstdint>

// Problem constants
#define BB 16
#define PP 8192
#define NN (BB*PP)          // 131072
#define FEAT 6
#define MM 128              // MAX_TOKENS
#define DD 768              // TOKEN_DIM
#define KK 16               // kNN
#define GG (BB*MM)          // 2048 groups
#define RR (GG*KK)          // 32768 gathered rows

typedef __nv_bfloat16 bf16;

// ---------------- scratch (static device globals; no allocs) ----------------
__device__ float4 g_pts[NN];
__device__ float4 g_cent[GG];
__device__ int    g_knn[RR];
__device__ bf16   g_h1h[(size_t)RR*256],  g_h1l[(size_t)RR*256];
__device__ bf16   g_h2h[(size_t)RR*512],  g_h2l[(size_t)RR*512];
__device__ bf16   g_h3h[(size_t)RR*768],  g_h3l[(size_t)RR*768];
__device__ float  g_emb[(size_t)RR*768];
__device__ bf16   g_plh[(size_t)GG*768],  g_pll[(size_t)GG*768];
__device__ bf16   g_t1h[(size_t)GG*768],  g_t1l[(size_t)GG*768];
// transposed weights Wt[N,K] split hi/lo
__device__ bf16   g_w2h[512*256],  g_w2l[512*256];
__device__ bf16   g_w3h[768*512],  g_w3l[768*512];
__device__ bf16   g_w4h[768*768],  g_w4l[768*768];
__device__ bf16   g_wa1h[768*768], g_wa1l[768*768];
__device__ bf16   g_wa2h[768*768], g_wa2l[768*768];

__device__ __forceinline__ void split_bf16(float v, bf16& hi, bf16& lo) {
    hi = __float2bfloat16_rn(v);
    lo = __float2bfloat16_rn(v - __bfloat162float(hi));
}

__device__ __forceinline__ uint32_t smem_u32(const void* p) {
    uint32_t a;
    asm("{ .reg .u64 t; cvta.to.shared.u64 t, %1; cvt.u32.u64 %0, t; }" : "=r"(a) : "l"(p));
    return a;
}
__device__ __forceinline__ void cpasync16(uint32_t dst, const void* src) {
    asm volatile("cp.async.cg.shared.global [%0], [%1], 16;"
                 :: "r"(dst), "l"(__cvta_generic_to_global(src)));
}
#define CP_COMMIT() asm volatile("cp.async.commit_group;" ::: "memory")
#define CP_WAIT(n)  asm volatile("cp.async.wait_group %0;" :: "n"(n) : "memory")

__device__ __forceinline__ void ldmx4(uint32_t* r, uint32_t addr) {
    asm volatile("ldmatrix.sync.aligned.m8n8.x4.shared.b16 {%0,%1,%2,%3}, [%4];"
                 : "=r"(r[0]), "=r"(r[1]), "=r"(r[2]), "=r"(r[3]) : "r"(addr));
}
__device__ __forceinline__ void mma16816(float* d, const uint32_t* a, const uint32_t* b) {
    asm volatile("mma.sync.aligned.m16n8k16.row.col.f32.bf16.bf16.f32 "
                 "{%0,%1,%2,%3}, {%4,%5,%6,%7}, {%8,%9}, {%0,%1,%2,%3};"
                 : "+f"(d[0]), "+f"(d[1]), "+f"(d[2]), "+f"(d[3])
                 : "r"(a[0]), "r"(a[1]), "r"(a[2]), "r"(a[3]), "r"(b[0]), "r"(b[1]));
}

// ---------------- kernel 0: pack coordinates[:,1:5] into float4 -------------
__global__ void pack_kernel(const float* __restrict__ coords) {
    int i = blockIdx.x * 256 + threadIdx.x;
    if (i < NN) {
        const float* c = coords + (size_t)i * 5;
        g_pts[i] = make_float4(c[1], c[2], c[3], c[4]);
    }
}

// ---------------- merged weight conversion (ONE launch) ---------------------
// W[K,N] fp32 -> Wt[N,K] bf16 hi/lo, for all 5 weight matrices.
#define S2 (256*512)
#define S3 (512*768)
#define S4 (768*768)
__global__ void convw_all_kernel(const float* __restrict__ W2,
                                 const float* __restrict__ W3,
                                 const float* __restrict__ W4,
                                 const float* __restrict__ Wa1,
                                 const float* __restrict__ Wa2) {
    int i = blockIdx.x * 256 + threadIdx.x;
    const float* W; bf16 *Wh, *Wl; int Kd, Nd; int base;
    if (i < S2)                       { W = W2;  Wh = g_w2h;  Wl = g_w2l;  Kd = 256; Nd = 512; base = 0; }
    else if (i < S2 + S3)             { W = W3;  Wh = g_w3h;  Wl = g_w3l;  Kd = 512; Nd = 768; base = S2; }
    else if (i < S2 + S3 + S4)        { W = W4;  Wh = g_w4h;  Wl = g_w4l;  Kd = 768; Nd = 768; base = S2 + S3; }
    else if (i < S2 + S3 + 2*S4)      { W = Wa1; Wh = g_wa1h; Wl = g_wa1l; Kd = 768; Nd = 768; base = S2 + S3 + S4; }
    else if (i < S2 + S3 + 3*S4)      { W = Wa2; Wh = g_wa2h; Wl = g_wa2l; Kd = 768; Nd = 768; base = S2 + S3 + 2*S4; }
    else return;
    int e = i - base;
    int k = e / Nd, n = e % Nd;
    bf16 hi, lo; split_bf16(W[e], hi, lo);
    Wh[(size_t)n * Kd + k] = hi;
    Wl[(size_t)n * Kd + k] = lo;
}
#define CONVW_TOTAL (S2 + S3 + 3*S4)

// ---------------- kernel 1: farthest point sampling (one block/batch) -------
__global__ __launch_bounds__(1024) void fps_kernel() {
    int b = blockIdx.x;
    int tid = threadIdx.x;
    const float4* pb = g_pts + (size_t)b * PP;

    float4 pt[8];
    float dmin[8];
#pragma unroll
    for (int t = 0; t < 8; ++t) { pt[t] = pb[tid + t * 1024]; dmin[t] = 1e30f; }

    __shared__ float4 s_last;
    __shared__ float s_v[32];
    __shared__ int   s_i[32];

    if (tid == 0) { s_last = pb[0]; g_cent[b * MM + 0] = pb[0]; }
    __syncthreads();

    for (int it = 1; it < MM; ++it) {
        float4 c = s_last;
        float bv = -1.0f; int bi = 0;
#pragma unroll
        for (int t = 0; t < 8; ++t) {
            float dx = pt[t].x - c.x, dy = pt[t].y - c.y;
            float dz = pt[t].z - c.z, dw = pt[t].w - c.w;
            float d = dx*dx + dy*dy + dz*dz + dw*dw;
            dmin[t] = fminf(dmin[t], d);
            int gi = tid + t * 1024;
            if (dmin[t] > bv) { bv = dmin[t]; bi = gi; }
        }
#pragma unroll
        for (int off = 16; off; off >>= 1) {
            float ov = __shfl_down_sync(0xffffffffu, bv, off);
            int   oi = __shfl_down_sync(0xffffffffu, bi, off);
            if (ov > bv || (ov == bv && oi < bi)) { bv = ov; bi = oi; }
        }
        if ((tid & 31) == 0) { s_v[tid >> 5] = bv; s_i[tid >> 5] = bi; }
        __syncthreads();
        if (tid < 32) {
            bv = s_v[tid]; bi = s_i[tid];
#pragma unroll
            for (int off = 16; off; off >>= 1) {
                float ov = __shfl_down_sync(0xffffffffu, bv, off);
                int   oi = __shfl_down_sync(0xffffffffu, bi, off);
                if (ov > bv || (ov == bv && oi < bi)) { bv = ov; bi = oi; }
            }
            if (tid == 0) {
                float4 np = pb[bi];
                s_last = np;
                g_cent[b * MM + it] = np;
            }
        }
        __syncthreads();
    }
}

// ---------------- kernel 2: kNN (one warp per (b,m), top-16 smallest) -------
__global__ __launch_bounds__(256) void knn_kernel() {
    __shared__ float sv[8][512];
    __shared__ int   si[8][512];
    int w = threadIdx.x >> 5;
    int lane = threadIdx.x & 31;
    int g = blockIdx.x * 8 + w;
    int b = g >> 7;
    const float4* pb = g_pts + (size_t)b * PP;
    float4 c = g_cent[g];

    float bv[16]; int bi[16];
#pragma unroll
    for (int i = 0; i < 16; ++i) { bv[i] = 1e30f; bi[i] = 0; }
    float worst = 1e30f; int wpos = 0;

    for (int p = lane; p < PP; p += 32) {
        float4 q = __ldg(&pb[p]);
        float dx = q.x - c.x, dy = q.y - c.y, dz = q.z - c.z, dw = q.w - c.w;
        float d = dx*dx + dy*dy + dz*dz + dw*dw;
        if (d < worst) {
#pragma unroll
            for (int i = 0; i < 16; ++i) if (i == wpos) { bv[i] = d; bi[i] = p; }
            worst = -1.0f;
#pragma unroll
            for (int i = 0; i < 16; ++i) if (bv[i] > worst) { worst = bv[i]; wpos = i; }
        }
    }
#pragma unroll
    for (int i = 0; i < 16; ++i) { sv[w][lane * 16 + i] = bv[i]; si[w][lane * 16 + i] = bi[i]; }
    __syncwarp();

    for (int r = 0; r < 16; ++r) {
        float mv = 1e30f; int me = 0;
#pragma unroll
        for (int j = 0; j < 16; ++j) {
            int e = j * 32 + lane;
            float v = sv[w][e];
            if (v < mv) { mv = v; me = e; }
        }
#pragma unroll
        for (int off = 16; off; off >>= 1) {
            float ov = __shfl_xor_sync(0xffffffffu, mv, off);
            int   oe = __shfl_xor_sync(0xffffffffu, me, off);
            if (ov < mv || (ov == mv && oe < me)) { mv = ov; me = oe; }
        }
        if (lane == 0) { g_knn[g * 16 + r] = si[w][me]; sv[w][me] = 1e30f; }
        __syncwarp();
    }
}

// ---------------- kernel 3: gather + layer1 (6 -> 256, relu), split out -----
__global__ __launch_bounds__(256) void layer1_kernel(const float* __restrict__ feats,
                                                     const float* __restrict__ W1,
                                                     const float* __restrict__ b1) {
    int j = threadIdx.x;
    int r0 = blockIdx.x * 8;
    __shared__ float sf[8][6];
    if (threadIdx.x < 48) {
        int rr = threadIdx.x / 6, f = threadIdx.x % 6;
        int r = r0 + rr;
        int g = r >> 4;
        int b = g >> 7;
        int p = g_knn[r];
        sf[rr][f] = feats[((size_t)b * PP + p) * 6 + f];
    }
    float w[6];
#pragma unroll
    for (int f = 0; f < 6; ++f) w[f] = W1[f * 256 + j];
    float bj = b1[j];
    __syncthreads();
#pragma unroll
    for (int rr = 0; rr < 8; ++rr) {
        float acc = bj;
#pragma unroll
        for (int f = 0; f < 6; ++f) acc += sf[rr][f] * w[f];
        float v = fmaxf(acc, 0.0f);
        bf16 hi, lo; split_bf16(v, hi, lo);
        size_t o = (size_t)(r0 + rr) * 256 + j;
        g_h1h[o] = hi; g_h1l[o] = lo;
    }
}

// ---------------- HMMA bf16 split GEMM (3-stage cp.async pipeline) ----------
// C[M,N] = act(A @ W + bias); A hi/lo [Mrows,K] bf16 row-major,
// W transposed hi/lo [N,K]. CTA tile 128x128, BK=32, 8 warps (warp 32m x 64n).
// K' = 3K phases: (Ahi,Whi), (Ahi,Wlo), (Alo,Whi). fp32 accum in registers.
#define ROWB 80          // padded smem row stride in bytes (32 bf16 = 64B data)
#define STG  10240       // 128 rows * 80 B
#define STAGES 3
template<bool RELU, bool WF32, bool WSPLIT>
__global__ __launch_bounds__(256) void gemm_kernel(
    const bf16* __restrict__ Ahi, const bf16* __restrict__ Alo,
    const bf16* __restrict__ Bhi, const bf16* __restrict__ Blo,
    const float* __restrict__ bias,
    float* __restrict__ Cf, bf16* __restrict__ Chi, bf16* __restrict__ Clo,
    int Kd, int Nd)
{
    __shared__ __align__(16) char smem[STAGES * 2 * STG];   // [stage][A/B]
    uint32_t sb = smem_u32(smem);

    const int tid  = threadIdx.x;
    const int wid  = tid >> 5;
    const int lane = tid & 31;
    const int bm = blockIdx.y * 128;
    const int bn = blockIdx.x * 128;
    const int wm = (wid & 3) * 32;     // warp m offset
    const int wn = (wid >> 2) * 64;    // warp n offset

    const int kchunks = Kd >> 5;       // 32-wide chunks per phase
    const int C = 3 * kchunks;

    float acc[2][8][4];
#pragma unroll
    for (int i = 0; i < 2; ++i)
#pragma unroll
        for (int j = 0; j < 8; ++j)
#pragma unroll
            for (int q = 0; q < 4; ++q) acc[i][j][q] = 0.0f;

    // per-thread load mapping: row = tid/2, 32B at (tid&1)*32B within 64B row
    const int lrow = tid >> 1;
    const int lofs = (tid & 1) * 16;   // element offset (16 bf16 = 32B)

    auto load_chunk = [&](int c, int s) {
        int phase = c / kchunks;
        int kk = c - phase * kchunks;
        const bf16* Ap = (phase < 2) ? Ahi : Alo;
        const bf16* Bp = (phase == 1) ? Blo : Bhi;
        const bf16* asrc = Ap + ((size_t)(bm + lrow)) * Kd + kk * 32 + lofs;
        const bf16* bsrc = Bp + ((size_t)(bn + lrow)) * Kd + kk * 32 + lofs;
        uint32_t ad = sb + s * 2 * STG + lrow * ROWB + lofs * 2;
        uint32_t bd = ad + STG;
        cpasync16(ad, asrc);       cpasync16(ad + 16, asrc + 8);
        cpasync16(bd, bsrc);       cpasync16(bd + 16, bsrc + 8);
        CP_COMMIT();
    };

    // ldmatrix lane addressing (constant per thread)
    const int a_r = lane & 15;                 // m within 16
    const int a_c = (lane >> 4) << 3;          // k 0/8
    const int b_r = ((lane >> 4) << 3) + (lane & 7);   // n within 16
    const int b_c = ((lane >> 3) & 1) << 3;            // k 0/8

    load_chunk(0, 0);
    load_chunk(1, 1);

    int slot = 0;
    for (int c = 0; c < C; ++c) {
        CP_WAIT(1);            // group c complete (<=1 group in flight)
        __syncthreads();       // also: all threads done computing on slot (c-1)%3
        if (c + 2 < C) load_chunk(c + 2, (c + 2) % STAGES);

        uint32_t Ab = sb + slot * 2 * STG;
        uint32_t Bb = Ab + STG;
#pragma unroll
        for (int k16 = 0; k16 < 2; ++k16) {
            int k0 = k16 * 16;
            uint32_t a[2][4];
#pragma unroll
            for (int mt = 0; mt < 2; ++mt)
                ldmx4(a[mt], Ab + (wm + mt * 16 + a_r) * ROWB + (k0 + a_c) * 2);
            uint32_t b[4][4];
#pragma unroll
            for (int nt = 0; nt < 4; ++nt)
                ldmx4(b[nt], Bb + (wn + nt * 16 + b_r) * ROWB + (k0 + b_c) * 2);
#pragma unroll
            for (int mt = 0; mt < 2; ++mt)
#pragma unroll
                for (int nt = 0; nt < 4; ++nt) {
                    mma16816(acc[mt][nt * 2 + 0], a[mt], &b[nt][0]);
                    mma16816(acc[mt][nt * 2 + 1], a[mt], &b[nt][2]);
                }
        }
        slot = (slot + 1 == STAGES) ? 0 : slot + 1;
    }

    // epilogue
    const int r0 = lane >> 2;
    const int c0 = (lane & 3) * 2;
#pragma unroll
    for (int mt = 0; mt < 2; ++mt) {
#pragma unroll
        for (int nt8 = 0; nt8 < 8; ++nt8) {
            float* d = acc[mt][nt8];
            int gr = bm + wm + mt * 16 + r0;
            int gc = bn + wn + nt8 * 8 + c0;
#pragma unroll
            for (int q = 0; q < 4; ++q) {
                int rr = gr + (q >> 1) * 8;
                int cc = gc + (q & 1);
                float v = d[q] + __ldg(&bias[cc]);
                if (RELU) v = fmaxf(v, 0.0f);
                size_t o = (size_t)rr * Nd + cc;
                if (WF32) Cf[o] = v;
                if (WSPLIT) { bf16 hi, lo; split_bf16(v, hi, lo); Chi[o] = hi; Clo[o] = lo; }
            }
        }
    }
}

// ---------------- kernel: max pool over K=16, split output ------------------
__global__ void pool_kernel() {
    int i = blockIdx.x * 256 + threadIdx.x;
    if (i >= GG * 768) return;
    int g = i / 768, j = i % 768;
    const float* e = g_emb + ((size_t)g * 16) * 768 + j;
    float m = e[0];
#pragma unroll
    for (int k = 1; k < 16; ++k) m = fmaxf(m, e[(size_t)k * 768]);
    bf16 hi, lo; split_bf16(m, hi, lo);
    g_plh[i] = hi; g_pll[i] = lo;
}

// ---------------- epilogue: centroids + masks + tail ------------------------
__global__ void epilogue_kernel(float* __restrict__ out, int extra) {
    int i = blockIdx.x * 256 + threadIdx.x;
    if (i >= extra) return;
    const int T0 = GG * 768;
    float v;
    if (i < GG * 4) {
        const float4 c = g_cent[i >> 2];
        int comp = i & 3;
        v = (comp == 0) ? c.x : (comp == 1) ? c.y : (comp == 2) ? c.z : c.w;
    } else if (i < GG * 4 + GG) {
        v = 1.0f;
    } else {
        v = 0.0f;
    }
    out[T0 + i] = v;
}

// ---------------- host launcher ---------------------------------------------
template<typename T> static T* sym(const void* s) { void* p = nullptr; cudaGetSymbolAddress(&p, s); return (T*)p; }

extern "C" void kernel_launch(void* const* d_in, const int* in_sizes, int n_in,
                              void* d_out, int out_size) {
    const float* coords = (const float*)d_in[0];
    const float* feats  = (const float*)d_in[1];
    const float* W1 = (const float*)d_in[2];
    const float* b1 = (const float*)d_in[3];
    const float* W2 = (const float*)d_in[4];
    const float* b2 = (const float*)d_in[5];
    const float* W3 = (const float*)d_in[6];
    const float* b3 = (const float*)d_in[7];
    const float* W4 = (const float*)d_in[8];
    const float* b4 = (const float*)d_in[9];
    const float* Wa1 = (const float*)d_in[10];
    const float* ba1 = (const float*)d_in[11];
    const float* Wa2 = (const float*)d_in[12];
    const float* ba2 = (const float*)d_in[13];
    float* out = (float*)d_out;

    bf16 *h1h = sym<bf16>(g_h1h), *h1l = sym<bf16>(g_h1l);
    bf16 *h2h = sym<bf16>(g_h2h), *h2l = sym<bf16>(g_h2l);
    bf16 *h3h = sym<bf16>(g_h3h), *h3l = sym<bf16>(g_h3l);
    float *emb = sym<float>(g_emb);
    bf16 *plh = sym<bf16>(g_plh), *pll = sym<bf16>(g_pll);
    bf16 *t1h = sym<bf16>(g_t1h), *t1l = sym<bf16>(g_t1l);
    bf16 *w2h = sym<bf16>(g_w2h), *w2l = sym<bf16>(g_w2l);
    bf16 *w3h = sym<bf16>(g_w3h), *w3l = sym<bf16>(g_w3l);
    bf16 *w4h = sym<bf16>(g_w4h), *w4l = sym<bf16>(g_w4l);
    bf16 *wa1h = sym<bf16>(g_wa1h), *wa1l = sym<bf16>(g_wa1l);
    bf16 *wa2h = sym<bf16>(g_wa2h), *wa2l = sym<bf16>(g_wa2l);

    // launches 1-5 (ncu -s 5 -c 1 profiles launch #6 = first big GEMM)
    pack_kernel<<<(NN + 255) / 256, 256>>>(coords);
    convw_all_kernel<<<(CONVW_TOTAL + 255) / 256, 256>>>(W2, W3, W4, Wa1, Wa2);
    fps_kernel<<<BB, 1024>>>();
    knn_kernel<<<GG / 8, 256>>>();
    layer1_kernel<<<RR / 8, 256>>>(feats, W1, b1);

    // launch #6: h2 = relu(h1 @ W2 + b2): [32768,256] x [256,512]
    gemm_kernel<true, false, true><<<dim3(512 / 128, RR / 128), 256>>>(
        h1h, h1l, w2h, w2l, b2, nullptr, h2h, h2l, 256, 512);
    // h3 = relu(h2 @ W3 + b3): [32768,512] x [512,768]
    gemm_kernel<true, false, true><<<dim3(768 / 128, RR / 128), 256>>>(
        h2h, h2l, w3h, w3l, b3, nullptr, h3h, h3l, 512, 768);
    // emb = h3 @ W4 + b4: [32768,768] x [768,768] -> fp32
    gemm_kernel<false, true, false><<<dim3(768 / 128, RR / 128), 256>>>(
        h3h, h3l, w4h, w4l, b4, emb, nullptr, nullptr, 768, 768);

    pool_kernel<<<(GG * 768 + 255) / 256, 256>>>();

    // t1 = relu(pool @ Wa1 + ba1): [2048,768] x [768,768]
    gemm_kernel<true, false, true><<<dim3(768 / 128, GG / 128), 256>>>(
        plh, pll, wa1h, wa1l, ba1, nullptr, t1h, t1l, 768, 768);
    // tokens = t1 @ Wa2 + ba2 -> d_out fp32
    gemm_kernel<false, true, false><<<dim3(768 / 128, GG / 128), 256>>>(
        t1h, t1l, wa2h, wa2l, ba2, out, nullptr, nullptr, 768, 768);

    int extra = out_size - GG * 768;
    if (extra > 0) {
        epilogue_kernel<<<(extra + 255) / 256, 256>>>(out, extra);
    }
}

// round 9
// speedup vs baseline: 1.6402x; 1.1051x over previous
#include <cuda_runtime.h>
#include <cuda_bf16.h>
#include <cstdint>

// Problem constants
#define BB 16
#define PP 8192
#define NN (BB*PP)          // 131072
#define FEAT 6
#define MM 128              // MAX_TOKENS
#define DD 768              // TOKEN_DIM
#define KK 16               // kNN
#define GG (BB*MM)          // 2048 groups
#define RR (GG*KK)          // 32768 gathered rows

typedef __nv_bfloat16 bf16;

// ---------------- scratch (static device globals; no allocs) ----------------
__device__ float4 g_pts[NN];
__device__ float4 g_cent[GG];
__device__ int    g_knn[RR];
__device__ bf16   g_h1h[(size_t)RR*256],  g_h1l[(size_t)RR*256];
__device__ bf16   g_h2h[(size_t)RR*512],  g_h2l[(size_t)RR*512];
__device__ bf16   g_h3h[(size_t)RR*768],  g_h3l[(size_t)RR*768];
__device__ float  g_emb[(size_t)RR*768];
__device__ bf16   g_plh[(size_t)GG*768],  g_pll[(size_t)GG*768];
__device__ bf16   g_t1h[(size_t)GG*768],  g_t1l[(size_t)GG*768];
// transposed weights Wt[N,K] split hi/lo
__device__ bf16   g_w2h[512*256],  g_w2l[512*256];
__device__ bf16   g_w3h[768*512],  g_w3l[768*512];
__device__ bf16   g_w4h[768*768],  g_w4l[768*768];
__device__ bf16   g_wa1h[768*768], g_wa1l[768*768];
__device__ bf16   g_wa2h[768*768], g_wa2l[768*768];

__device__ __forceinline__ void split_bf16(float v, bf16& hi, bf16& lo) {
    hi = __float2bfloat16_rn(v);
    lo = __float2bfloat16_rn(v - __bfloat162float(hi));
}
__device__ __forceinline__ uint32_t pack_bf(bf16 a, bf16 b) {
    return (uint32_t)__bfloat16_as_ushort(a) | ((uint32_t)__bfloat16_as_ushort(b) << 16);
}

__device__ __forceinline__ uint32_t smem_u32(const void* p) {
    uint32_t a;
    asm("{ .reg .u64 t; cvta.to.shared.u64 t, %1; cvt.u32.u64 %0, t; }" : "=r"(a) : "l"(p));
    return a;
}
__device__ __forceinline__ void cpasync16(uint32_t dst, const void* src) {
    asm volatile("cp.async.cg.shared.global [%0], [%1], 16;"
                 :: "r"(dst), "l"(__cvta_generic_to_global(src)));
}
#define CP_COMMIT() asm volatile("cp.async.commit_group;" ::: "memory")
#define CP_WAIT(n)  asm volatile("cp.async.wait_group %0;" :: "n"(n) : "memory")

__device__ __forceinline__ void ldmx4(uint32_t* r, uint32_t addr) {
    asm volatile("ldmatrix.sync.aligned.m8n8.x4.shared.b16 {%0,%1,%2,%3}, [%4];"
                 : "=r"(r[0]), "=r"(r[1]), "=r"(r[2]), "=r"(r[3]) : "r"(addr));
}
__device__ __forceinline__ void mma16816(float* d, const uint32_t* a, const uint32_t* b) {
    asm volatile("mma.sync.aligned.m16n8k16.row.col.f32.bf16.bf16.f32 "
                 "{%0,%1,%2,%3}, {%4,%5,%6,%7}, {%8,%9}, {%0,%1,%2,%3};"
                 : "+f"(d[0]), "+f"(d[1]), "+f"(d[2]), "+f"(d[3])
                 : "r"(a[0]), "r"(a[1]), "r"(a[2]), "r"(a[3]), "r"(b[0]), "r"(b[1]));
}

// ---------------- kernel 1: FPS (+ packs points for knn), one block/batch ---
__global__ __launch_bounds__(1024) void fps_kernel(const float* __restrict__ coords) {
    int b = blockIdx.x;
    int tid = threadIdx.x;
    const size_t base = (size_t)b * PP;

    float4 pt[8];
    float dmin[8];
#pragma unroll
    for (int t = 0; t < 8; ++t) {
        size_t i = base + tid + t * 1024;
        const float* c = coords + i * 5;
        pt[t] = make_float4(c[1], c[2], c[3], c[4]);
        g_pts[i] = pt[t];                 // pack for knn
        dmin[t] = 1e30f;
    }

    __shared__ float4 s_last;
    __shared__ float s_v[32];
    __shared__ int   s_i[32];

    if (tid == 0) { s_last = pt[0]; g_cent[b * MM + 0] = pt[0]; }
    __syncthreads();

    for (int it = 1; it < MM; ++it) {
        float4 c = s_last;
        float bv = -1.0f; int bi = 0;
#pragma unroll
        for (int t = 0; t < 8; ++t) {
            float dx = pt[t].x - c.x, dy = pt[t].y - c.y;
            float dz = pt[t].z - c.z, dw = pt[t].w - c.w;
            float d = dx*dx + dy*dy + dz*dz + dw*dw;
            dmin[t] = fminf(dmin[t], d);
            int gi = tid + t * 1024;
            if (dmin[t] > bv) { bv = dmin[t]; bi = gi; }
        }
#pragma unroll
        for (int off = 16; off; off >>= 1) {
            float ov = __shfl_down_sync(0xffffffffu, bv, off);
            int   oi = __shfl_down_sync(0xffffffffu, bi, off);
            if (ov > bv || (ov == bv && oi < bi)) { bv = ov; bi = oi; }
        }
        if ((tid & 31) == 0) { s_v[tid >> 5] = bv; s_i[tid >> 5] = bi; }
        __syncthreads();
        if (tid < 32) {
            bv = s_v[tid]; bi = s_i[tid];
#pragma unroll
            for (int off = 16; off; off >>= 1) {
                float ov = __shfl_down_sync(0xffffffffu, bv, off);
                int   oi = __shfl_down_sync(0xffffffffu, bi, off);
                if (ov > bv || (ov == bv && oi < bi)) { bv = ov; bi = oi; }
            }
            if (tid == 0) {
                float4 np = g_pts[base + bi];
                s_last = np;
                g_cent[b * MM + it] = np;
            }
        }
        __syncthreads();
    }
}

// ---------------- kernel 2: kNN, 4-way point split per query ----------------
// Block = 8 warps = 2 queries x 4 splits. Each warp scans 2048 points,
// per-lane top16 -> per-warp top16 -> cross-split 64 -> final top16.
#define SPLITS 4
#define SPTS (PP / SPLITS)     // 2048
__global__ __launch_bounds__(256) void knn_kernel() {
    __shared__ float sv[8][512];
    __shared__ int   si[8][512];
    __shared__ float fv[2][64];
    __shared__ int   fi[2][64];
    int w = threadIdx.x >> 5;
    int lane = threadIdx.x & 31;
    int qloc = w >> 2;                 // 0..1
    int s = w & 3;                     // split
    int g = blockIdx.x * 2 + qloc;     // query < 2048
    int b = g >> 7;
    const float4* pb = g_pts + (size_t)b * PP + s * SPTS;
    float4 c = g_cent[g];

    float bv[16]; int bi[16];
#pragma unroll
    for (int i = 0; i < 16; ++i) { bv[i] = 1e30f; bi[i] = 0; }
    float worst = 1e30f; int wpos = 0;

    for (int p = lane; p < SPTS; p += 32) {
        float4 q = __ldg(&pb[p]);
        float dx = q.x - c.x, dy = q.y - c.y, dz = q.z - c.z, dw = q.w - c.w;
        float d = dx*dx + dy*dy + dz*dz + dw*dw;
        if (d < worst) {
            int pg = s * SPTS + p;
#pragma unroll
            for (int i = 0; i < 16; ++i) if (i == wpos) { bv[i] = d; bi[i] = pg; }
            worst = -1.0f;
#pragma unroll
            for (int i = 0; i < 16; ++i) if (bv[i] > worst) { worst = bv[i]; wpos = i; }
        }
    }
#pragma unroll
    for (int i = 0; i < 16; ++i) { sv[w][lane * 16 + i] = bv[i]; si[w][lane * 16 + i] = bi[i]; }
    __syncwarp();

    // per-warp: select 16 smallest of 512 -> fv/fi[qloc][s*16 + r]
    for (int r = 0; r < 16; ++r) {
        float mv = 1e30f; int me = 0;
#pragma unroll
        for (int j = 0; j < 16; ++j) {
            int e = j * 32 + lane;
            float v = sv[w][e];
            if (v < mv) { mv = v; me = e; }
        }
#pragma unroll
        for (int off = 16; off; off >>= 1) {
            float ov = __shfl_xor_sync(0xffffffffu, mv, off);
            int   oe = __shfl_xor_sync(0xffffffffu, me, off);
            if (ov < mv || (ov == mv && oe < me)) { mv = ov; me = oe; }
        }
        if (lane == 0) {
            fv[qloc][s * 16 + r] = mv;
            fi[qloc][s * 16 + r] = si[w][me];
            sv[w][me] = 1e30f;
        }
        __syncwarp();
    }
    __syncthreads();

    // final: split-0 warp of each query merges 64 -> 16
    if (s == 0) {
        for (int r = 0; r < 16; ++r) {
            float v1 = fv[qloc][lane], v2 = fv[qloc][lane + 32];
            float mv; int me;
            if (v1 <= v2) { mv = v1; me = lane; } else { mv = v2; me = lane + 32; }
#pragma unroll
            for (int off = 16; off; off >>= 1) {
                float ov = __shfl_xor_sync(0xffffffffu, mv, off);
                int   oe = __shfl_xor_sync(0xffffffffu, me, off);
                if (ov < mv || (ov == mv && oe < me)) { mv = ov; me = oe; }
            }
            if (lane == 0) {
                g_knn[g * 16 + r] = fi[qloc][me];
                fv[qloc][me] = 1e30f;
            }
            __syncwarp();
        }
    }
}

// ---------------- kernel 3: fused [layer1 gather+GEMV] + [weight convert] ---
#define S2 (256*512)
#define S3 (512*768)
#define S4 (768*768)
#define CONVW_TOTAL (S2 + S3 + 3*S4)
#define L1_BLOCKS (RR / 8)                       // 4096
#define CW_BLOCKS ((CONVW_TOTAL + 255) / 256)    // 8960
__global__ __launch_bounds__(256) void mid_kernel(
    const float* __restrict__ feats,
    const float* __restrict__ W1, const float* __restrict__ b1,
    const float* __restrict__ W2, const float* __restrict__ W3,
    const float* __restrict__ W4, const float* __restrict__ Wa1,
    const float* __restrict__ Wa2)
{
    if (blockIdx.x < L1_BLOCKS) {
        // ---- layer1: gather + 6->256 + relu + split ----
        int j = threadIdx.x;
        int r0 = blockIdx.x * 8;
        __shared__ float sf[8][6];
        if (threadIdx.x < 48) {
            int rr = threadIdx.x / 6, f = threadIdx.x % 6;
            int r = r0 + rr;
            int g = r >> 4;
            int b = g >> 7;
            int p = g_knn[r];
            sf[rr][f] = feats[((size_t)b * PP + p) * 6 + f];
        }
        float w[6];
#pragma unroll
        for (int f = 0; f < 6; ++f) w[f] = W1[f * 256 + j];
        float bj = b1[j];
        __syncthreads();
#pragma unroll
        for (int rr = 0; rr < 8; ++rr) {
            float acc = bj;
#pragma unroll
            for (int f = 0; f < 6; ++f) acc += sf[rr][f] * w[f];
            float v = fmaxf(acc, 0.0f);
            bf16 hi, lo; split_bf16(v, hi, lo);
            size_t o = (size_t)(r0 + rr) * 256 + j;
            g_h1h[o] = hi; g_h1l[o] = lo;
        }
    } else {
        // ---- weight conversion: W[K,N] fp32 -> Wt[N,K] bf16 hi/lo ----
        int i = (blockIdx.x - L1_BLOCKS) * 256 + threadIdx.x;
        const float* W; bf16 *Wh, *Wl; int Kd, Nd; int base;
        if (i < S2)                  { W = W2;  Wh = g_w2h;  Wl = g_w2l;  Kd = 256; Nd = 512; base = 0; }
        else if (i < S2 + S3)        { W = W3;  Wh = g_w3h;  Wl = g_w3l;  Kd = 512; Nd = 768; base = S2; }
        else if (i < S2 + S3 + S4)   { W = W4;  Wh = g_w4h;  Wl = g_w4l;  Kd = 768; Nd = 768; base = S2 + S3; }
        else if (i < S2 + S3 + 2*S4) { W = Wa1; Wh = g_wa1h; Wl = g_wa1l; Kd = 768; Nd = 768; base = S2 + S3 + S4; }
        else if (i < S2 + S3 + 3*S4) { W = Wa2; Wh = g_wa2h; Wl = g_wa2l; Kd = 768; Nd = 768; base = S2 + S3 + 2*S4; }
        else return;
        int e = i - base;
        int k = e / Nd, n = e % Nd;
        bf16 hi, lo; split_bf16(W[e], hi, lo);
        Wh[(size_t)n * Kd + k] = hi;
        Wl[(size_t)n * Kd + k] = lo;
    }
}

// ---------------- HMMA bf16 split GEMM (3-stage cp.async pipeline) ----------
#define ROWB 80          // padded smem row stride in bytes (32 bf16 = 64B data)
#define STG  10240       // 128 rows * 80 B
#define STAGES 3
template<bool RELU, bool WF32, bool WSPLIT>
__global__ __launch_bounds__(256) void gemm_kernel(
    const bf16* __restrict__ Ahi, const bf16* __restrict__ Alo,
    const bf16* __restrict__ Bhi, const bf16* __restrict__ Blo,
    const float* __restrict__ bias,
    float* __restrict__ Cf, bf16* __restrict__ Chi, bf16* __restrict__ Clo,
    int Kd, int Nd)
{
    __shared__ __align__(16) char smem[STAGES * 2 * STG];   // [stage][A/B]
    uint32_t sb = smem_u32(smem);

    const int tid  = threadIdx.x;
    const int wid  = tid >> 5;
    const int lane = tid & 31;
    const int bm = blockIdx.y * 128;
    const int bn = blockIdx.x * 128;
    const int wm = (wid & 3) * 32;     // warp m offset
    const int wn = (wid >> 2) * 64;    // warp n offset

    const int kchunks = Kd >> 5;       // 32-wide chunks per phase
    const int C = 3 * kchunks;

    float acc[2][8][4];
#pragma unroll
    for (int i = 0; i < 2; ++i)
#pragma unroll
        for (int j = 0; j < 8; ++j)
#pragma unroll
            for (int q = 0; q < 4; ++q) acc[i][j][q] = 0.0f;

    const int lrow = tid >> 1;
    const int lofs = (tid & 1) * 16;   // element offset (16 bf16 = 32B)

    auto load_chunk = [&](int c, int s) {
        int phase = c / kchunks;
        int kk = c - phase * kchunks;
        const bf16* Ap = (phase < 2) ? Ahi : Alo;
        const bf16* Bp = (phase == 1) ? Blo : Bhi;
        const bf16* asrc = Ap + ((size_t)(bm + lrow)) * Kd + kk * 32 + lofs;
        const bf16* bsrc = Bp + ((size_t)(bn + lrow)) * Kd + kk * 32 + lofs;
        uint32_t ad = sb + s * 2 * STG + lrow * ROWB + lofs * 2;
        uint32_t bd = ad + STG;
        cpasync16(ad, asrc);       cpasync16(ad + 16, asrc + 8);
        cpasync16(bd, bsrc);       cpasync16(bd + 16, bsrc + 8);
        CP_COMMIT();
    };

    const int a_r = lane & 15;
    const int a_c = (lane >> 4) << 3;
    const int b_r = ((lane >> 4) << 3) + (lane & 7);
    const int b_c = ((lane >> 3) & 1) << 3;

    load_chunk(0, 0);
    load_chunk(1, 1);

    int slot = 0;
    for (int c = 0; c < C; ++c) {
        CP_WAIT(1);
        __syncthreads();
        if (c + 2 < C) load_chunk(c + 2, (c + 2) % STAGES);

        uint32_t Ab = sb + slot * 2 * STG;
        uint32_t Bb = Ab + STG;
#pragma unroll
        for (int k16 = 0; k16 < 2; ++k16) {
            int k0 = k16 * 16;
            uint32_t a[2][4];
#pragma unroll
            for (int mt = 0; mt < 2; ++mt)
                ldmx4(a[mt], Ab + (wm + mt * 16 + a_r) * ROWB + (k0 + a_c) * 2);
            uint32_t b[4][4];
#pragma unroll
            for (int nt = 0; nt < 4; ++nt)
                ldmx4(b[nt], Bb + (wn + nt * 16 + b_r) * ROWB + (k0 + b_c) * 2);
#pragma unroll
            for (int mt = 0; mt < 2; ++mt)
#pragma unroll
                for (int nt = 0; nt < 4; ++nt) {
                    mma16816(acc[mt][nt * 2 + 0], a[mt], &b[nt][0]);
                    mma16816(acc[mt][nt * 2 + 1], a[mt], &b[nt][2]);
                }
        }
        slot = (slot + 1 == STAGES) ? 0 : slot + 1;
    }

    // vectorized epilogue: pairs (cols gc, gc+1)
    const int r0 = lane >> 2;
    const int c0 = (lane & 3) * 2;
#pragma unroll
    for (int mt = 0; mt < 2; ++mt) {
#pragma unroll
        for (int nt8 = 0; nt8 < 8; ++nt8) {
            float* d = acc[mt][nt8];
            int gr = bm + wm + mt * 16 + r0;
            int gc = bn + wn + nt8 * 8 + c0;
            float bb0 = __ldg(&bias[gc]);
            float bb1 = __ldg(&bias[gc + 1]);
#pragma unroll
            for (int h = 0; h < 2; ++h) {
                int rr = gr + h * 8;
                float v0 = d[h * 2 + 0] + bb0;
                float v1 = d[h * 2 + 1] + bb1;
                if (RELU) { v0 = fmaxf(v0, 0.0f); v1 = fmaxf(v1, 0.0f); }
                size_t o = (size_t)rr * Nd + gc;
                if (WF32) {
                    *(float2*)(Cf + o) = make_float2(v0, v1);
                }
                if (WSPLIT) {
                    bf16 h0, l0, h1, l1;
                    split_bf16(v0, h0, l0);
                    split_bf16(v1, h1, l1);
                    *(uint32_t*)(Chi + o) = pack_bf(h0, h1);
                    *(uint32_t*)(Clo + o) = pack_bf(l0, l1);
                }
            }
        }
    }
}

// ---------------- kernel: max pool over K=16, split output ------------------
__global__ void pool_kernel() {
    int i = blockIdx.x * 256 + threadIdx.x;
    if (i >= GG * 768) return;
    int g = i / 768, j = i % 768;
    const float* e = g_emb + ((size_t)g * 16) * 768 + j;
    float m = e[0];
#pragma unroll
    for (int k = 1; k < 16; ++k) m = fmaxf(m, e[(size_t)k * 768]);
    bf16 hi, lo; split_bf16(m, hi, lo);
    g_plh[i] = hi; g_pll[i] = lo;
}

// ---------------- epilogue: centroids + masks + tail ------------------------
__global__ void epilogue_kernel(float* __restrict__ out, int extra) {
    int i = blockIdx.x * 256 + threadIdx.x;
    if (i >= extra) return;
    const int T0 = GG * 768;
    float v;
    if (i < GG * 4) {
        const float4 c = g_cent[i >> 2];
        int comp = i & 3;
        v = (comp == 0) ? c.x : (comp == 1) ? c.y : (comp == 2) ? c.z : c.w;
    } else if (i < GG * 4 + GG) {
        v = 1.0f;
    } else {
        v = 0.0f;
    }
    out[T0 + i] = v;
}

// ---------------- host launcher ---------------------------------------------
template<typename T> static T* sym(const void* s) { void* p = nullptr; cudaGetSymbolAddress(&p, s); return (T*)p; }

extern "C" void kernel_launch(void* const* d_in, const int* in_sizes, int n_in,
                              void* d_out, int out_size) {
    const float* coords = (const float*)d_in[0];
    const float* feats  = (const float*)d_in[1];
    const float* W1 = (const float*)d_in[2];
    const float* b1 = (const float*)d_in[3];
    const float* W2 = (const float*)d_in[4];
    const float* b2 = (const float*)d_in[5];
    const float* W3 = (const float*)d_in[6];
    const float* b3 = (const float*)d_in[7];
    const float* W4 = (const float*)d_in[8];
    const float* b4 = (const float*)d_in[9];
    const float* Wa1 = (const float*)d_in[10];
    const float* ba1 = (const float*)d_in[11];
    const float* Wa2 = (const float*)d_in[12];
    const float* ba2 = (const float*)d_in[13];
    float* out = (float*)d_out;

    bf16 *h1h = sym<bf16>(g_h1h), *h1l = sym<bf16>(g_h1l);
    bf16 *h2h = sym<bf16>(g_h2h), *h2l = sym<bf16>(g_h2l);
    bf16 *h3h = sym<bf16>(g_h3h), *h3l = sym<bf16>(g_h3l);
    float *emb = sym<float>(g_emb);
    bf16 *plh = sym<bf16>(g_plh), *pll = sym<bf16>(g_pll);
    bf16 *t1h = sym<bf16>(g_t1h), *t1l = sym<bf16>(g_t1l);
    bf16 *w2h = sym<bf16>(g_w2h), *w2l = sym<bf16>(g_w2l);
    bf16 *w3h = sym<bf16>(g_w3h), *w3l = sym<bf16>(g_w3l);
    bf16 *w4h = sym<bf16>(g_w4h), *w4l = sym<bf16>(g_w4l);
    bf16 *wa1h = sym<bf16>(g_wa1h), *wa1l = sym<bf16>(g_wa1l);
    bf16 *wa2h = sym<bf16>(g_wa2h), *wa2l = sym<bf16>(g_wa2l);

    // my launches 1-3 (harness injects 2 -> global 3-5); #4 = gemm1 = global #6 (ncu -s 5)
    fps_kernel<<<BB, 1024>>>(coords);
    knn_kernel<<<GG / 2, 256>>>();
    mid_kernel<<<L1_BLOCKS + CW_BLOCKS, 256>>>(feats, W1, b1, W2, W3, W4, Wa1, Wa2);

    // gemm1: h2 = relu(h1 @ W2 + b2): [32768,256] x [256,512]
    gemm_kernel<true, false, true><<<dim3(512 / 128, RR / 128), 256>>>(
        h1h, h1l, w2h, w2l, b2, nullptr, h2h, h2l, 256, 512);
    // gemm2: h3 = relu(h2 @ W3 + b3): [32768,512] x [512,768]
    gemm_kernel<true, false, true><<<dim3(768 / 128, RR / 128), 256>>>(
        h2h, h2l, w3h, w3l, b3, nullptr, h3h, h3l, 512, 768);
    // gemm3: emb = h3 @ W4 + b4: [32768,768] x [768,768] -> fp32
    gemm_kernel<false, true, false><<<dim3(768 / 128, RR / 128), 256>>>(
        h3h, h3l, w4h, w4l, b4, emb, nullptr, nullptr, 768, 768);

    pool_kernel<<<(GG * 768 + 255) / 256, 256>>>();

    // t1 = relu(pool @ Wa1 + ba1): [2048,768] x [768,768]
    gemm_kernel<true, false, true><<<dim3(768 / 128, GG / 128), 256>>>(
        plh, pll, wa1h, wa1l, ba1, nullptr, t1h, t1l, 768, 768);
    // tokens = t1 @ Wa2 + ba2 -> d_out fp32
    gemm_kernel<false, true, false><<<dim3(768 / 128, GG / 128), 256>>>(
        t1h, t1l, wa2h, wa2l, ba2, out, nullptr, nullptr, 768, 768);

    int extra = out_size - GG * 768;
    if (extra > 0) {
        epilogue_kernel<<<(extra + 255) / 256, 256>>>(out, extra);
    }
}

// round 11
// speedup vs baseline: 1.6406x; 1.0002x over previous
#include <cuda_runtime.h>
#include <cuda_bf16.h>
#include <cstdint>

// Problem constants
#define BB 16
#define PP 8192
#define NN (BB*PP)          // 131072
#define FEAT 6
#define MM 128              // MAX_TOKENS
#define DD 768              // TOKEN_DIM
#define KK 16               // kNN
#define GG (BB*MM)          // 2048 groups
#define RR (GG*KK)          // 32768 gathered rows

typedef __nv_bfloat16 bf16;

// ---------------- scratch (static device globals; no allocs) ----------------
__device__ float4 g_pts[NN];
__device__ float4 g_cent[GG];
__device__ int    g_knn[RR];
__device__ bf16   g_h1h[(size_t)RR*256],  g_h1l[(size_t)RR*256];
__device__ bf16   g_h2h[(size_t)RR*512],  g_h2l[(size_t)RR*512];
__device__ bf16   g_h3h[(size_t)RR*768],  g_h3l[(size_t)RR*768];
__device__ bf16   g_plh[(size_t)GG*768],  g_pll[(size_t)GG*768];
__device__ bf16   g_t1h[(size_t)GG*768],  g_t1l[(size_t)GG*768];
// transposed weights Wt[N,K] split hi/lo
__device__ bf16   g_w2h[512*256],  g_w2l[512*256];
__device__ bf16   g_w3h[768*512],  g_w3l[768*512];
__device__ bf16   g_w4h[768*768],  g_w4l[768*768];
__device__ bf16   g_wa1h[768*768], g_wa1l[768*768];
__device__ bf16   g_wa2h[768*768], g_wa2l[768*768];

__device__ __forceinline__ void split_bf16(float v, bf16& hi, bf16& lo) {
    hi = __float2bfloat16_rn(v);
    lo = __float2bfloat16_rn(v - __bfloat162float(hi));
}
__device__ __forceinline__ uint32_t pack_bf(bf16 a, bf16 b) {
    return (uint32_t)__bfloat16_as_ushort(a) | ((uint32_t)__bfloat16_as_ushort(b) << 16);
}

__device__ __forceinline__ uint32_t smem_u32(const void* p) {
    uint32_t a;
    asm("{ .reg .u64 t; cvta.to.shared.u64 t, %1; cvt.u32.u64 %0, t; }" : "=r"(a) : "l"(p));
    return a;
}
__device__ __forceinline__ void cpasync16(uint32_t dst, const void* src) {
    asm volatile("cp.async.cg.shared.global [%0], [%1], 16;"
                 :: "r"(dst), "l"(__cvta_generic_to_global(src)));
}
#define CP_COMMIT() asm volatile("cp.async.commit_group;" ::: "memory")
#define CP_WAIT(n)  asm volatile("cp.async.wait_group %0;" :: "n"(n) : "memory")

__device__ __forceinline__ void ldmx4(uint32_t* r, uint32_t addr) {
    asm volatile("ldmatrix.sync.aligned.m8n8.x4.shared.b16 {%0,%1,%2,%3}, [%4];"
                 : "=r"(r[0]), "=r"(r[1]), "=r"(r[2]), "=r"(r[3]) : "r"(addr));
}
__device__ __forceinline__ void mma16816(float* d, const uint32_t* a, const uint32_t* b) {
    asm volatile("mma.sync.aligned.m16n8k16.row.col.f32.bf16.bf16.f32 "
                 "{%0,%1,%2,%3}, {%4,%5,%6,%7}, {%8,%9}, {%0,%1,%2,%3};"
                 : "+f"(d[0]), "+f"(d[1]), "+f"(d[2]), "+f"(d[3])
                 : "r"(a[0]), "r"(a[1]), "r"(a[2]), "r"(a[3]), "r"(b[0]), "r"(b[1]));
}

// ---------------- kernel 1: FPS (+ packs points for knn), one block/batch ---
__global__ __launch_bounds__(1024) void fps_kernel(const float* __restrict__ coords) {
    int b = blockIdx.x;
    int tid = threadIdx.x;
    const size_t base = (size_t)b * PP;

    float4 pt[8];
    float dmin[8];
#pragma unroll
    for (int t = 0; t < 8; ++t) {
        size_t i = base + tid + t * 1024;
        const float* c = coords + i * 5;
        pt[t] = make_float4(c[1], c[2], c[3], c[4]);
        g_pts[i] = pt[t];                 // pack for knn
        dmin[t] = 1e30f;
    }

    __shared__ float4 s_last;
    __shared__ float s_v[32];
    __shared__ int   s_i[32];

    if (tid == 0) { s_last = pt[0]; g_cent[b * MM + 0] = pt[0]; }
    __syncthreads();

    for (int it = 1; it < MM; ++it) {
        float4 c = s_last;
        float bv = -1.0f; int bi = 0;
#pragma unroll
        for (int t = 0; t < 8; ++t) {
            float dx = pt[t].x - c.x, dy = pt[t].y - c.y;
            float dz = pt[t].z - c.z, dw = pt[t].w - c.w;
            float d = dx*dx + dy*dy + dz*dz + dw*dw;
            dmin[t] = fminf(dmin[t], d);
            int gi = tid + t * 1024;
            if (dmin[t] > bv) { bv = dmin[t]; bi = gi; }
        }
#pragma unroll
        for (int off = 16; off; off >>= 1) {
            float ov = __shfl_down_sync(0xffffffffu, bv, off);
            int   oi = __shfl_down_sync(0xffffffffu, bi, off);
            if (ov > bv || (ov == bv && oi < bi)) { bv = ov; bi = oi; }
        }
        if ((tid & 31) == 0) { s_v[tid >> 5] = bv; s_i[tid >> 5] = bi; }
        __syncthreads();
        if (tid < 32) {
            bv = s_v[tid]; bi = s_i[tid];
#pragma unroll
            for (int off = 16; off; off >>= 1) {
                float ov = __shfl_down_sync(0xffffffffu, bv, off);
                int   oi = __shfl_down_sync(0xffffffffu, bi, off);
                if (ov > bv || (ov == bv && oi < bi)) { bv = ov; bi = oi; }
            }
            if (tid == 0) {
                float4 np = g_pts[base + bi];
                s_last = np;
                g_cent[b * MM + it] = np;
            }
        }
        __syncthreads();
    }
}

// ---------------- kernel 2: kNN, 4-way point split per query ----------------
#define SPLITS 4
#define SPTS (PP / SPLITS)     // 2048
__global__ __launch_bounds__(256) void knn_kernel() {
    __shared__ float sv[8][512];
    __shared__ int   si[8][512];
    __shared__ float fv[2][64];
    __shared__ int   fi[2][64];
    int w = threadIdx.x >> 5;
    int lane = threadIdx.x & 31;
    int qloc = w >> 2;                 // 0..1
    int s = w & 3;                     // split
    int g = blockIdx.x * 2 + qloc;     // query < 2048
    int b = g >> 7;
    const float4* pb = g_pts + (size_t)b * PP + s * SPTS;
    float4 c = g_cent[g];

    float bv[16]; int bi[16];
#pragma unroll
    for (int i = 0; i < 16; ++i) { bv[i] = 1e30f; bi[i] = 0; }
    float worst = 1e30f; int wpos = 0;

    for (int p = lane; p < SPTS; p += 32) {
        float4 q = __ldg(&pb[p]);
        float dx = q.x - c.x, dy = q.y - c.y, dz = q.z - c.z, dw = q.w - c.w;
        float d = dx*dx + dy*dy + dz*dz + dw*dw;
        if (d < worst) {
            int pg = s * SPTS + p;
#pragma unroll
            for (int i = 0; i < 16; ++i) if (i == wpos) { bv[i] = d; bi[i] = pg; }
            worst = -1.0f;
#pragma unroll
            for (int i = 0; i < 16; ++i) if (bv[i] > worst) { worst = bv[i]; wpos = i; }
        }
    }
#pragma unroll
    for (int i = 0; i < 16; ++i) { sv[w][lane * 16 + i] = bv[i]; si[w][lane * 16 + i] = bi[i]; }
    __syncwarp();

    for (int r = 0; r < 16; ++r) {
        float mv = 1e30f; int me = 0;
#pragma unroll
        for (int j = 0; j < 16; ++j) {
            int e = j * 32 + lane;
            float v = sv[w][e];
            if (v < mv) { mv = v; me = e; }
        }
#pragma unroll
        for (int off = 16; off; off >>= 1) {
            float ov = __shfl_xor_sync(0xffffffffu, mv, off);
            int   oe = __shfl_xor_sync(0xffffffffu, me, off);
            if (ov < mv || (ov == mv && oe < me)) { mv = ov; me = oe; }
        }
        if (lane == 0) {
            fv[qloc][s * 16 + r] = mv;
            fi[qloc][s * 16 + r] = si[w][me];
            sv[w][me] = 1e30f;
        }
        __syncwarp();
    }
    __syncthreads();

    if (s == 0) {
        for (int r = 0; r < 16; ++r) {
            float v1 = fv[qloc][lane], v2 = fv[qloc][lane + 32];
            float mv; int me;
            if (v1 <= v2) { mv = v1; me = lane; } else { mv = v2; me = lane + 32; }
#pragma unroll
            for (int off = 16; off; off >>= 1) {
                float ov = __shfl_xor_sync(0xffffffffu, mv, off);
                int   oe = __shfl_xor_sync(0xffffffffu, me, off);
                if (ov < mv || (ov == mv && oe < me)) { mv = ov; me = oe; }
            }
            if (lane == 0) {
                g_knn[g * 16 + r] = fi[qloc][me];
                fv[qloc][me] = 1e30f;
            }
            __syncwarp();
        }
    }
}

// ---------------- kernel 3: fused [layer1 gather+GEMV] + [weight convert] ---
#define S2 (256*512)
#define S3 (512*768)
#define S4 (768*768)
#define CONVW_TOTAL (S2 + S3 + 3*S4)
#define L1_BLOCKS (RR / 8)                       // 4096
#define CW_BLOCKS ((CONVW_TOTAL + 255) / 256)    // 8960
__global__ __launch_bounds__(256) void mid_kernel(
    const float* __restrict__ feats,
    const float* __restrict__ W1, const float* __restrict__ b1,
    const float* __restrict__ W2, const float* __restrict__ W3,
    const float* __restrict__ W4, const float* __restrict__ Wa1,
    const float* __restrict__ Wa2)
{
    if (blockIdx.x < L1_BLOCKS) {
        int j = threadIdx.x;
        int r0 = blockIdx.x * 8;
        __shared__ float sf[8][6];
        if (threadIdx.x < 48) {
            int rr = threadIdx.x / 6, f = threadIdx.x % 6;
            int r = r0 + rr;
            int g = r >> 4;
            int b = g >> 7;
            int p = g_knn[r];
            sf[rr][f] = feats[((size_t)b * PP + p) * 6 + f];
        }
        float w[6];
#pragma unroll
        for (int f = 0; f < 6; ++f) w[f] = W1[f * 256 + j];
        float bj = b1[j];
        __syncthreads();
#pragma unroll
        for (int rr = 0; rr < 8; ++rr) {
            float acc = bj;
#pragma unroll
            for (int f = 0; f < 6; ++f) acc += sf[rr][f] * w[f];
            float v = fmaxf(acc, 0.0f);
            bf16 hi, lo; split_bf16(v, hi, lo);
            size_t o = (size_t)(r0 + rr) * 256 + j;
            g_h1h[o] = hi; g_h1l[o] = lo;
        }
    } else {
        int i = (blockIdx.x - L1_BLOCKS) * 256 + threadIdx.x;
        const float* W; bf16 *Wh, *Wl; int Kd, Nd; int base;
        if (i < S2)                  { W = W2;  Wh = g_w2h;  Wl = g_w2l;  Kd = 256; Nd = 512; base = 0; }
        else if (i < S2 + S3)        { W = W3;  Wh = g_w3h;  Wl = g_w3l;  Kd = 512; Nd = 768; base = S2; }
        else if (i < S2 + S3 + S4)   { W = W4;  Wh = g_w4h;  Wl = g_w4l;  Kd = 768; Nd = 768; base = S2 + S3; }
        else if (i < S2 + S3 + 2*S4) { W = Wa1; Wh = g_wa1h; Wl = g_wa1l; Kd = 768; Nd = 768; base = S2 + S3 + S4; }
        else if (i < S2 + S3 + 3*S4) { W = Wa2; Wh = g_wa2h; Wl = g_wa2l; Kd = 768; Nd = 768; base = S2 + S3 + 2*S4; }
        else return;
        int e = i - base;
        int k = e / Nd, n = e % Nd;
        bf16 hi, lo; split_bf16(W[e], hi, lo);
        Wh[(size_t)n * Kd + k] = hi;
        Wl[(size_t)n * Kd + k] = lo;
    }
}

// ---------------- HMMA bf16 split GEMM: BK=64, 3-stage, dyn smem ------------
// C[M,N] = act(A @ W + bias); A hi/lo [Mrows,K] bf16 row-major,
// W transposed hi/lo [N,K]. CTA tile 128x128, BK=64, 8 warps (warp 32m x 64n).
// K' = 3K phases: (Ahi,Whi), (Ahi,Wlo), (Alo,Whi). fp32 accum in registers.
// WPOOL: stage fp32 tile in smem, max over 16-row groups, emit pooled split.
#define ROWB 144         // padded smem row stride (64 bf16 = 128B data + 16 pad)
#define STG  18432       // 128 rows * 144 B
#define STAGES 3
#define DSMEM (STAGES * 2 * STG)   // 110592
#define STP 132          // fp32 pool-staging row stride (floats)
template<bool RELU, bool WF32, bool WSPLIT, bool WPOOL>
__global__ __launch_bounds__(256, 2) void gemm_kernel(
    const bf16* __restrict__ Ahi, const bf16* __restrict__ Alo,
    const bf16* __restrict__ Bhi, const bf16* __restrict__ Blo,
    const float* __restrict__ bias,
    float* __restrict__ Cf, bf16* __restrict__ Chi, bf16* __restrict__ Clo,
    int Kd, int Nd)
{
    extern __shared__ __align__(16) char smem[];
    uint32_t sb = smem_u32(smem);

    const int tid  = threadIdx.x;
    const int wid  = tid >> 5;
    const int lane = tid & 31;
    const int bm = blockIdx.y * 128;
    const int bn = blockIdx.x * 128;
    const int wm = (wid & 3) * 32;     // warp m offset
    const int wn = (wid >> 2) * 64;    // warp n offset

    const int kchunks = Kd >> 6;       // 64-wide chunks per phase
    const int C = 3 * kchunks;

    float acc[2][8][4];
#pragma unroll
    for (int i = 0; i < 2; ++i)
#pragma unroll
        for (int j = 0; j < 8; ++j)
#pragma unroll
            for (int q = 0; q < 4; ++q) acc[i][j][q] = 0.0f;

    // loader: thread covers 64B of one row: row = tid/2, byte off = (tid&1)*64
    const int lrow = tid >> 1;
    const int lofs = (tid & 1) * 32;   // element offset (32 bf16 = 64B)

    auto load_chunk = [&](int c, int s) {
        int phase = c / kchunks;
        int kk = c - phase * kchunks;
        const bf16* Ap = (phase < 2) ? Ahi : Alo;
        const bf16* Bp = (phase == 1) ? Blo : Bhi;
        const bf16* asrc = Ap + ((size_t)(bm + lrow)) * Kd + kk * 64 + lofs;
        const bf16* bsrc = Bp + ((size_t)(bn + lrow)) * Kd + kk * 64 + lofs;
        uint32_t ad = sb + s * 2 * STG + lrow * ROWB + lofs * 2;
        uint32_t bd = ad + STG;
#pragma unroll
        for (int g2 = 0; g2 < 4; ++g2) {
            cpasync16(ad + g2 * 16, asrc + g2 * 8);
            cpasync16(bd + g2 * 16, bsrc + g2 * 8);
        }
        CP_COMMIT();
    };

    const int a_r = lane & 15;
    const int a_c = (lane >> 4) << 3;
    const int b_r = ((lane >> 4) << 3) + (lane & 7);
    const int b_c = ((lane >> 3) & 1) << 3;

    load_chunk(0, 0);
    load_chunk(1, 1);

    int slot = 0;
    for (int c = 0; c < C; ++c) {
        CP_WAIT(1);
        __syncthreads();
        if (c + 2 < C) load_chunk(c + 2, (c + 2) % STAGES);

        uint32_t Ab = sb + slot * 2 * STG;
        uint32_t Bb = Ab + STG;
#pragma unroll
        for (int k16 = 0; k16 < 4; ++k16) {
            int k0 = k16 * 16;
            uint32_t a[2][4];
#pragma unroll
            for (int mt = 0; mt < 2; ++mt)
                ldmx4(a[mt], Ab + (wm + mt * 16 + a_r) * ROWB + (k0 + a_c) * 2);
            uint32_t b[4][4];
#pragma unroll
            for (int nt = 0; nt < 4; ++nt)
                ldmx4(b[nt], Bb + (wn + nt * 16 + b_r) * ROWB + (k0 + b_c) * 2);
#pragma unroll
            for (int mt = 0; mt < 2; ++mt)
#pragma unroll
                for (int nt = 0; nt < 4; ++nt) {
                    mma16816(acc[mt][nt * 2 + 0], a[mt], &b[nt][0]);
                    mma16816(acc[mt][nt * 2 + 1], a[mt], &b[nt][2]);
                }
        }
        slot = (slot + 1 == STAGES) ? 0 : slot + 1;
    }

    const int r0 = lane >> 2;
    const int c0 = (lane & 3) * 2;

    if (WPOOL) {
        // stage fp32 tile in smem, pool over 16-row groups, emit split bf16
        float* st = (float*)smem;
        __syncthreads();   // all warps done reading tiles
#pragma unroll
        for (int mt = 0; mt < 2; ++mt) {
#pragma unroll
            for (int nt8 = 0; nt8 < 8; ++nt8) {
                float* d = acc[mt][nt8];
                int lr = wm + mt * 16 + r0;
                int lc = wn + nt8 * 8 + c0;
                float bb0 = __ldg(&bias[bn + lc]);
                float bb1 = __ldg(&bias[bn + lc + 1]);
#pragma unroll
                for (int h = 0; h < 2; ++h) {
                    st[(lr + h * 8) * STP + lc]     = d[h * 2 + 0] + bb0;
                    st[(lr + h * 8) * STP + lc + 1] = d[h * 2 + 1] + bb1;
                }
            }
        }
        __syncthreads();
        for (int o = tid; o < 8 * 128; o += 256) {
            int gloc = o >> 7, col = o & 127;
            const float* p = st + (gloc * 16) * STP + col;
            float m = p[0];
#pragma unroll
            for (int k = 1; k < 16; ++k) m = fmaxf(m, p[k * STP]);
            size_t idx = (size_t)((bm >> 4) + gloc) * 768 + bn + col;
            bf16 hi, lo; split_bf16(m, hi, lo);
            g_plh[idx] = hi; g_pll[idx] = lo;
        }
    } else {
#pragma unroll
        for (int mt = 0; mt < 2; ++mt) {
#pragma unroll
            for (int nt8 = 0; nt8 < 8; ++nt8) {
                float* d = acc[mt][nt8];
                int gr = bm + wm + mt * 16 + r0;
                int gc = bn + wn + nt8 * 8 + c0;
                float bb0 = __ldg(&bias[gc]);
                float bb1 = __ldg(&bias[gc + 1]);
#pragma unroll
                for (int h = 0; h < 2; ++h) {
                    int rr = gr + h * 8;
                    float v0 = d[h * 2 + 0] + bb0;
                    float v1 = d[h * 2 + 1] + bb1;
                    if (RELU) { v0 = fmaxf(v0, 0.0f); v1 = fmaxf(v1, 0.0f); }
                    size_t o = (size_t)rr * Nd + gc;
                    if (WF32) {
                        *(float2*)(Cf + o) = make_float2(v0, v1);
                    }
                    if (WSPLIT) {
                        bf16 h0, l0, h1, l1;
                        split_bf16(v0, h0, l0);
                        split_bf16(v1, h1, l1);
                        *(uint32_t*)(Chi + o) = pack_bf(h0, h1);
                        *(uint32_t*)(Clo + o) = pack_bf(l0, l1);
                    }
                }
            }
        }
    }
}

// ---------------- epilogue: centroids + masks + tail ------------------------
__global__ void epilogue_kernel(float* __restrict__ out, int extra) {
    int i = blockIdx.x * 256 + threadIdx.x;
    if (i >= extra) return;
    const int T0 = GG * 768;
    float v;
    if (i < GG * 4) {
        const float4 c = g_cent[i >> 2];
        int comp = i & 3;
        v = (comp == 0) ? c.x : (comp == 1) ? c.y : (comp == 2) ? c.z : c.w;
    } else if (i < GG * 4 + GG) {
        v = 1.0f;
    } else {
        v = 0.0f;
    }
    out[T0 + i] = v;
}

// ---------------- host launcher ---------------------------------------------
template<typename T> static T* sym(const void* s) { void* p = nullptr; cudaGetSymbolAddress(&p, s); return (T*)p; }

extern "C" void kernel_launch(void* const* d_in, const int* in_sizes, int n_in,
                              void* d_out, int out_size) {
    const float* coords = (const float*)d_in[0];
    const float* feats  = (const float*)d_in[1];
    const float* W1 = (const float*)d_in[2];
    const float* b1 = (const float*)d_in[3];
    const float* W2 = (const float*)d_in[4];
    const float* b2 = (const float*)d_in[5];
    const float* W3 = (const float*)d_in[6];
    const float* b3 = (const float*)d_in[7];
    const float* W4 = (const float*)d_in[8];
    const float* b4 = (const float*)d_in[9];
    const float* Wa1 = (const float*)d_in[10];
    const float* ba1 = (const float*)d_in[11];
    const float* Wa2 = (const float*)d_in[12];
    const float* ba2 = (const float*)d_in[13];
    float* out = (float*)d_out;

    bf16 *h1h = sym<bf16>(g_h1h), *h1l = sym<bf16>(g_h1l);
    bf16 *h2h = sym<bf16>(g_h2h), *h2l = sym<bf16>(g_h2l);
    bf16 *h3h = sym<bf16>(g_h3h), *h3l = sym<bf16>(g_h3l);
    bf16 *plh = sym<bf16>(g_plh), *pll = sym<bf16>(g_pll);
    bf16 *t1h = sym<bf16>(g_t1h), *t1l = sym<bf16>(g_t1l);
    bf16 *w2h = sym<bf16>(g_w2h), *w2l = sym<bf16>(g_w2l);
    bf16 *w3h = sym<bf16>(g_w3h), *w3l = sym<bf16>(g_w3l);
    bf16 *w4h = sym<bf16>(g_w4h), *w4l = sym<bf16>(g_w4l);
    bf16 *wa1h = sym<bf16>(g_wa1h), *wa1l = sym<bf16>(g_wa1l);
    bf16 *wa2h = sym<bf16>(g_wa2h), *wa2l = sym<bf16>(g_wa2l);

    // opt-in smem (idempotent; host-side, legal during capture)
    cudaFuncSetAttribute(gemm_kernel<true, false, true, false>,
                         cudaFuncAttributeMaxDynamicSharedMemorySize, DSMEM);
    cudaFuncSetAttribute(gemm_kernel<false, false, false, true>,
                         cudaFuncAttributeMaxDynamicSharedMemorySize, DSMEM);
    cudaFuncSetAttribute(gemm_kernel<false, true, false, false>,
                         cudaFuncAttributeMaxDynamicSharedMemorySize, DSMEM);

    // my launches 1-3 (harness injects 2 -> global 3-5); #4 = gemm1 = global #6 (ncu -s 5)
    fps_kernel<<<BB, 1024>>>(coords);
    knn_kernel<<<GG / 2, 256>>>();
    mid_kernel<<<L1_BLOCKS + CW_BLOCKS, 256>>>(feats, W1, b1, W2, W3, W4, Wa1, Wa2);

    // gemm1: h2 = relu(h1 @ W2 + b2): [32768,256] x [256,512]
    gemm_kernel<true, false, true, false><<<dim3(512 / 128, RR / 128), 256, DSMEM>>>(
        h1h, h1l, w2h, w2l, b2, nullptr, h2h, h2l, 256, 512);
    // gemm2: h3 = relu(h2 @ W3 + b3): [32768,512] x [512,768]
    gemm_kernel<true, false, true, false><<<dim3(768 / 128, RR / 128), 256, DSMEM>>>(
        h2h, h2l, w3h, w3l, b3, nullptr, h3h, h3l, 512, 768);
    // gemm3: pooled = maxpool16(h3 @ W4 + b4): [32768,768] x [768,768] -> [2048,768] split
    gemm_kernel<false, false, false, true><<<dim3(768 / 128, RR / 128), 256, DSMEM>>>(
        h3h, h3l, w4h, w4l, b4, nullptr, nullptr, nullptr, 768, 768);

    // t1 = relu(pool @ Wa1 + ba1): [2048,768] x [768,768]
    gemm_kernel<true, false, true, false><<<dim3(768 / 128, GG / 128), 256, DSMEM>>>(
        plh, pll, wa1h, wa1l, ba1, nullptr, t1h, t1l, 768, 768);
    // tokens = t1 @ Wa2 + ba2 -> d_out fp32
    gemm_kernel<false, true, false, false><<<dim3(768 / 128, GG / 128), 256, DSMEM>>>(
        t1h, t1l, wa2h, wa2l, ba2, out, nullptr, nullptr, 768, 768);

    int extra = out_size - GG * 768;
    if (extra > 0) {
        epilogue_kernel<<<(extra + 255) / 256, 256>>>(out, extra);
    }
}

// round 13
// speedup vs baseline: 2.2020x; 1.3422x over previous
#include <cuda_runtime.h>
#include <cuda_fp16.h>
#include <cstdint>

// Problem constants
#define BB 16
#define PP 8192
#define NN (BB*PP)          // 131072
#define FEAT 6
#define MM 128              // MAX_TOKENS
#define DD 768              // TOKEN_DIM
#define KK 16               // kNN
#define GG (BB*MM)          // 2048 groups
#define RR (GG*KK)          // 32768 gathered rows

typedef __half hf;

// ---------------- scratch (static device globals; no allocs) ----------------
__device__ float4 g_pts[NN];
__device__ float4 g_cent[GG];
__device__ int    g_knn[RR];
__device__ hf     g_h1[(size_t)RR*256];
__device__ hf     g_h2[(size_t)RR*512];
__device__ hf     g_h3[(size_t)RR*768];
__device__ hf     g_pl[(size_t)GG*768];
__device__ hf     g_t1[(size_t)GG*768];
// transposed weights Wt[N,K] split hi/lo (fp16)
__device__ hf     g_w2h[512*256],  g_w2l[512*256];
__device__ hf     g_w3h[768*512],  g_w3l[768*512];
__device__ hf     g_w4h[768*768],  g_w4l[768*768];
__device__ hf     g_wa1h[768*768], g_wa1l[768*768];
__device__ hf     g_wa2h[768*768], g_wa2l[768*768];

__device__ __forceinline__ void split_h(float v, hf& hi, hf& lo) {
    hi = __float2half_rn(v);
    lo = __float2half_rn(v - __half2float(hi));
}
__device__ __forceinline__ uint32_t pack_h(hf a, hf b) {
    return (uint32_t)__half_as_ushort(a) | ((uint32_t)__half_as_ushort(b) << 16);
}

__device__ __forceinline__ uint32_t smem_u32(const void* p) {
    uint32_t a;
    asm("{ .reg .u64 t; cvta.to.shared.u64 t, %1; cvt.u32.u64 %0, t; }" : "=r"(a) : "l"(p));
    return a;
}
__device__ __forceinline__ void cpasync16(uint32_t dst, const void* src) {
    asm volatile("cp.async.cg.shared.global [%0], [%1], 16;"
                 :: "r"(dst), "l"(__cvta_generic_to_global(src)));
}
#define CP_COMMIT() asm volatile("cp.async.commit_group;" ::: "memory")
#define CP_WAIT(n)  asm volatile("cp.async.wait_group %0;" :: "n"(n) : "memory")

__device__ __forceinline__ void ldmx4(uint32_t* r, uint32_t addr) {
    asm volatile("ldmatrix.sync.aligned.m8n8.x4.shared.b16 {%0,%1,%2,%3}, [%4];"
                 : "=r"(r[0]), "=r"(r[1]), "=r"(r[2]), "=r"(r[3]) : "r"(addr));
}
__device__ __forceinline__ void mma16816(float* d, const uint32_t* a, const uint32_t* b) {
    asm volatile("mma.sync.aligned.m16n8k16.row.col.f32.f16.f16.f32 "
                 "{%0,%1,%2,%3}, {%4,%5,%6,%7}, {%8,%9}, {%0,%1,%2,%3};"
                 : "+f"(d[0]), "+f"(d[1]), "+f"(d[2]), "+f"(d[3])
                 : "r"(a[0]), "r"(a[1]), "r"(a[2]), "r"(a[3]), "r"(b[0]), "r"(b[1]));
}

// ---------------- kernel 1: FPS (+ packs points for knn), one block/batch ---
__global__ __launch_bounds__(1024) void fps_kernel(const float* __restrict__ coords) {
    int b = blockIdx.x;
    int tid = threadIdx.x;
    const size_t base = (size_t)b * PP;

    float4 pt[8];
    float dmin[8];
#pragma unroll
    for (int t = 0; t < 8; ++t) {
        size_t i = base + tid + t * 1024;
        const float* c = coords + i * 5;
        pt[t] = make_float4(c[1], c[2], c[3], c[4]);
        g_pts[i] = pt[t];                 // pack for knn
        dmin[t] = 1e30f;
    }

    __shared__ float4 s_last;
    __shared__ float s_v[32];
    __shared__ int   s_i[32];

    if (tid == 0) { s_last = pt[0]; g_cent[b * MM + 0] = pt[0]; }
    __syncthreads();

    for (int it = 1; it < MM; ++it) {
        float4 c = s_last;
        float bv = -1.0f; int bi = 0;
#pragma unroll
        for (int t = 0; t < 8; ++t) {
            float dx = pt[t].x - c.x, dy = pt[t].y - c.y;
            float dz = pt[t].z - c.z, dw = pt[t].w - c.w;
            float d = dx*dx + dy*dy + dz*dz + dw*dw;
            dmin[t] = fminf(dmin[t], d);
            int gi = tid + t * 1024;
            if (dmin[t] > bv) { bv = dmin[t]; bi = gi; }
        }
#pragma unroll
        for (int off = 16; off; off >>= 1) {
            float ov = __shfl_down_sync(0xffffffffu, bv, off);
            int   oi = __shfl_down_sync(0xffffffffu, bi, off);
            if (ov > bv || (ov == bv && oi < bi)) { bv = ov; bi = oi; }
        }
        if ((tid & 31) == 0) { s_v[tid >> 5] = bv; s_i[tid >> 5] = bi; }
        __syncthreads();
        if (tid < 32) {
            bv = s_v[tid]; bi = s_i[tid];
#pragma unroll
            for (int off = 16; off; off >>= 1) {
                float ov = __shfl_down_sync(0xffffffffu, bv, off);
                int   oi = __shfl_down_sync(0xffffffffu, bi, off);
                if (ov > bv || (ov == bv && oi < bi)) { bv = ov; bi = oi; }
            }
            if (tid == 0) {
                float4 np = g_pts[base + bi];
                s_last = np;
                g_cent[b * MM + it] = np;
            }
        }
        __syncthreads();
    }
}

// ---------------- kernel 2: kNN, 4-way point split per query ----------------
#define SPLITS 4
#define SPTS (PP / SPLITS)     // 2048
__global__ __launch_bounds__(256) void knn_kernel() {
    __shared__ float sv[8][512];
    __shared__ int   si[8][512];
    __shared__ float fv[2][64];
    __shared__ int   fi[2][64];
    int w = threadIdx.x >> 5;
    int lane = threadIdx.x & 31;
    int qloc = w >> 2;                 // 0..1
    int s = w & 3;                     // split
    int g = blockIdx.x * 2 + qloc;     // query < 2048
    int b = g >> 7;
    const float4* pb = g_pts + (size_t)b * PP + s * SPTS;
    float4 c = g_cent[g];

    float bv[16]; int bi[16];
#pragma unroll
    for (int i = 0; i < 16; ++i) { bv[i] = 1e30f; bi[i] = 0; }
    float worst = 1e30f; int wpos = 0;

    for (int p = lane; p < SPTS; p += 32) {
        float4 q = __ldg(&pb[p]);
        float dx = q.x - c.x, dy = q.y - c.y, dz = q.z - c.z, dw = q.w - c.w;
        float d = dx*dx + dy*dy + dz*dz + dw*dw;
        if (d < worst) {
            int pg = s * SPTS + p;
#pragma unroll
            for (int i = 0; i < 16; ++i) if (i == wpos) { bv[i] = d; bi[i] = pg; }
            worst = -1.0f;
#pragma unroll
            for (int i = 0; i < 16; ++i) if (bv[i] > worst) { worst = bv[i]; wpos = i; }
        }
    }
#pragma unroll
    for (int i = 0; i < 16; ++i) { sv[w][lane * 16 + i] = bv[i]; si[w][lane * 16 + i] = bi[i]; }
    __syncwarp();

    for (int r = 0; r < 16; ++r) {
        float mv = 1e30f; int me = 0;
#pragma unroll
        for (int j = 0; j < 16; ++j) {
            int e = j * 32 + lane;
            float v = sv[w][e];
            if (v < mv) { mv = v; me = e; }
        }
#pragma unroll
        for (int off = 16; off; off >>= 1) {
            float ov = __shfl_xor_sync(0xffffffffu, mv, off);
            int   oe = __shfl_xor_sync(0xffffffffu, me, off);
            if (ov < mv || (ov == mv && oe < me)) { mv = ov; me = oe; }
        }
        if (lane == 0) {
            fv[qloc][s * 16 + r] = mv;
            fi[qloc][s * 16 + r] = si[w][me];
            sv[w][me] = 1e30f;
        }
        __syncwarp();
    }
    __syncthreads();

    if (s == 0) {
        for (int r = 0; r < 16; ++r) {
            float v1 = fv[qloc][lane], v2 = fv[qloc][lane + 32];
            float mv; int me;
            if (v1 <= v2) { mv = v1; me = lane; } else { mv = v2; me = lane + 32; }
#pragma unroll
            for (int off = 16; off; off >>= 1) {
                float ov = __shfl_xor_sync(0xffffffffu, mv, off);
                int   oe = __shfl_xor_sync(0xffffffffu, me, off);
                if (ov < mv || (ov == mv && oe < me)) { mv = ov; me = oe; }
            }
            if (lane == 0) {
                g_knn[g * 16 + r] = fi[qloc][me];
                fv[qloc][me] = 1e30f;
            }
            __syncwarp();
        }
    }
}

// ---------------- kernel 3: fused [layer1 gather+GEMV] + [weight convert] ---
#define S2 (256*512)
#define S3 (512*768)
#define S4 (768*768)
#define CONVW_TOTAL (S2 + S3 + 3*S4)
#define L1_BLOCKS (RR / 8)                       // 4096
#define CW_BLOCKS ((CONVW_TOTAL + 255) / 256)    // 8960
__global__ __launch_bounds__(256) void mid_kernel(
    const float* __restrict__ feats,
    const float* __restrict__ W1, const float* __restrict__ b1,
    const float* __restrict__ W2, const float* __restrict__ W3,
    const float* __restrict__ W4, const float* __restrict__ Wa1,
    const float* __restrict__ Wa2)
{
    if (blockIdx.x < L1_BLOCKS) {
        int j = threadIdx.x;
        int r0 = blockIdx.x * 8;
        __shared__ float sf[8][6];
        if (threadIdx.x < 48) {
            int rr = threadIdx.x / 6, f = threadIdx.x % 6;
            int r = r0 + rr;
            int g = r >> 4;
            int b = g >> 7;
            int p = g_knn[r];
            sf[rr][f] = feats[((size_t)b * PP + p) * 6 + f];
        }
        float w[6];
#pragma unroll
        for (int f = 0; f < 6; ++f) w[f] = W1[f * 256 + j];
        float bj = b1[j];
        __syncthreads();
#pragma unroll
        for (int rr = 0; rr < 8; ++rr) {
            float acc = bj;
#pragma unroll
            for (int f = 0; f < 6; ++f) acc += sf[rr][f] * w[f];
            float v = fmaxf(acc, 0.0f);
            g_h1[(size_t)(r0 + rr) * 256 + j] = __float2half_rn(v);
        }
    } else {
        int i = (blockIdx.x - L1_BLOCKS) * 256 + threadIdx.x;
        const float* W; hf *Wh, *Wl; int Kd, Nd; int base;
        if (i < S2)                  { W = W2;  Wh = g_w2h;  Wl = g_w2l;  Kd = 256; Nd = 512; base = 0; }
        else if (i < S2 + S3)        { W = W3;  Wh = g_w3h;  Wl = g_w3l;  Kd = 512; Nd = 768; base = S2; }
        else if (i < S2 + S3 + S4)   { W = W4;  Wh = g_w4h;  Wl = g_w4l;  Kd = 768; Nd = 768; base = S2 + S3; }
        else if (i < S2 + S3 + 2*S4) { W = Wa1; Wh = g_wa1h; Wl = g_wa1l; Kd = 768; Nd = 768; base = S2 + S3 + S4; }
        else if (i < S2 + S3 + 3*S4) { W = Wa2; Wh = g_wa2h; Wl = g_wa2l; Kd = 768; Nd = 768; base = S2 + S3 + 2*S4; }
        else return;
        int e = i - base;
        int k = e / Nd, n = e % Nd;
        hf hi, lo; split_h(W[e], hi, lo);
        Wh[(size_t)n * Kd + k] = hi;
        Wl[(size_t)n * Kd + k] = lo;
    }
}

// ---------------- HMMA fp16 2-pass GEMM: BK=64, 3-stage, dyn smem ----------
// C[M,N] = act(A @ W + bias); A single fp16 [Mrows,K] row-major,
// W transposed hi/lo fp16 [N,K]. CTA tile 128x128, BK=64, 8 warps (32m x 64n).
// K' = 2K phases: (A,Whi), (A,Wlo). fp32 accum in registers.
// WPOOL: stage fp32 tile in smem, max over 16-row groups, emit pooled fp16.
#define ROWB 144         // padded smem row stride (64 hf = 128B data + 16 pad)
#define STG  18432       // 128 rows * 144 B
#define STAGES 3
#define DSMEM (STAGES * 2 * STG)   // 110592
#define STP 132          // fp32 pool-staging row stride (floats)
template<bool RELU, bool WF32, bool WH16, bool WPOOL>
__global__ __launch_bounds__(256, 2) void gemm_kernel(
    const hf* __restrict__ A,
    const hf* __restrict__ Bhi, const hf* __restrict__ Blo,
    const float* __restrict__ bias,
    float* __restrict__ Cf, hf* __restrict__ Ch,
    int Kd, int Nd)
{
    extern __shared__ __align__(16) char smem[];
    uint32_t sb = smem_u32(smem);

    const int tid  = threadIdx.x;
    const int wid  = tid >> 5;
    const int lane = tid & 31;
    const int bm = blockIdx.y * 128;
    const int bn = blockIdx.x * 128;
    const int wm = (wid & 3) * 32;     // warp m offset
    const int wn = (wid >> 2) * 64;    // warp n offset

    const int kchunks = Kd >> 6;       // 64-wide chunks per phase
    const int C = 2 * kchunks;

    float acc[2][8][4];
#pragma unroll
    for (int i = 0; i < 2; ++i)
#pragma unroll
        for (int j = 0; j < 8; ++j)
#pragma unroll
            for (int q = 0; q < 4; ++q) acc[i][j][q] = 0.0f;

    // loader: thread covers 64B of one row: row = tid/2, byte off = (tid&1)*64
    const int lrow = tid >> 1;
    const int lofs = (tid & 1) * 32;   // element offset (32 hf = 64B)

    auto load_chunk = [&](int c, int s) {
        int phase = c / kchunks;
        int kk = c - phase * kchunks;
        const hf* Bp = (phase == 0) ? Bhi : Blo;
        const hf* asrc = A  + ((size_t)(bm + lrow)) * Kd + kk * 64 + lofs;
        const hf* bsrc = Bp + ((size_t)(bn + lrow)) * Kd + kk * 64 + lofs;
        uint32_t ad = sb + s * 2 * STG + lrow * ROWB + lofs * 2;
        uint32_t bd = ad + STG;
#pragma unroll
        for (int g2 = 0; g2 < 4; ++g2) {
            cpasync16(ad + g2 * 16, asrc + g2 * 8);
            cpasync16(bd + g2 * 16, bsrc + g2 * 8);
        }
        CP_COMMIT();
    };

    const int a_r = lane & 15;
    const int a_c = (lane >> 4) << 3;
    const int b_r = ((lane >> 4) << 3) + (lane & 7);
    const int b_c = ((lane >> 3) & 1) << 3;

    load_chunk(0, 0);
    load_chunk(1, 1);

    int slot = 0;
    for (int c = 0; c < C; ++c) {
        CP_WAIT(1);
        __syncthreads();
        if (c + 2 < C) load_chunk(c + 2, (c + 2) % STAGES);

        uint32_t Ab = sb + slot * 2 * STG;
        uint32_t Bb = Ab + STG;
#pragma unroll
        for (int k16 = 0; k16 < 4; ++k16) {
            int k0 = k16 * 16;
            uint32_t a[2][4];
#pragma unroll
            for (int mt = 0; mt < 2; ++mt)
                ldmx4(a[mt], Ab + (wm + mt * 16 + a_r) * ROWB + (k0 + a_c) * 2);
            uint32_t b[4][4];
#pragma unroll
            for (int nt = 0; nt < 4; ++nt)
                ldmx4(b[nt], Bb + (wn + nt * 16 + b_r) * ROWB + (k0 + b_c) * 2);
#pragma unroll
            for (int mt = 0; mt < 2; ++mt)
#pragma unroll
                for (int nt = 0; nt < 4; ++nt) {
                    mma16816(acc[mt][nt * 2 + 0], a[mt], &b[nt][0]);
                    mma16816(acc[mt][nt * 2 + 1], a[mt], &b[nt][2]);
                }
        }
        slot = (slot + 1 == STAGES) ? 0 : slot + 1;
    }

    const int r0 = lane >> 2;
    const int c0 = (lane & 3) * 2;

    if (WPOOL) {
        // stage fp32 tile in smem, pool over 16-row groups, emit pooled fp16
        float* st = (float*)smem;
        __syncthreads();   // all warps done reading tiles
#pragma unroll
        for (int mt = 0; mt < 2; ++mt) {
#pragma unroll
            for (int nt8 = 0; nt8 < 8; ++nt8) {
                float* d = acc[mt][nt8];
                int lr = wm + mt * 16 + r0;
                int lc = wn + nt8 * 8 + c0;
                float bb0 = __ldg(&bias[bn + lc]);
                float bb1 = __ldg(&bias[bn + lc + 1]);
#pragma unroll
                for (int h = 0; h < 2; ++h) {
                    st[(lr + h * 8) * STP + lc]     = d[h * 2 + 0] + bb0;
                    st[(lr + h * 8) * STP + lc + 1] = d[h * 2 + 1] + bb1;
                }
            }
        }
        __syncthreads();
        for (int o = tid; o < 8 * 128; o += 256) {
            int gloc = o >> 7, col = o & 127;
            const float* p = st + (gloc * 16) * STP + col;
            float m = p[0];
#pragma unroll
            for (int k = 1; k < 16; ++k) m = fmaxf(m, p[k * STP]);
            size_t idx = (size_t)((bm >> 4) + gloc) * 768 + bn + col;
            g_pl[idx] = __float2half_rn(m);
        }
    } else {
#pragma unroll
        for (int mt = 0; mt < 2; ++mt) {
#pragma unroll
            for (int nt8 = 0; nt8 < 8; ++nt8) {
                float* d = acc[mt][nt8];
                int gr = bm + wm + mt * 16 + r0;
                int gc = bn + wn + nt8 * 8 + c0;
                float bb0 = __ldg(&bias[gc]);
                float bb1 = __ldg(&bias[gc + 1]);
#pragma unroll
                for (int h = 0; h < 2; ++h) {
                    int rr = gr + h * 8;
                    float v0 = d[h * 2 + 0] + bb0;
                    float v1 = d[h * 2 + 1] + bb1;
                    if (RELU) { v0 = fmaxf(v0, 0.0f); v1 = fmaxf(v1, 0.0f); }
                    size_t o = (size_t)rr * Nd + gc;
                    if (WF32) {
                        *(float2*)(Cf + o) = make_float2(v0, v1);
                    }
                    if (WH16) {
                        *(uint32_t*)(Ch + o) = pack_h(__float2half_rn(v0),
                                                      __float2half_rn(v1));
                    }
                }
            }
        }
    }
}

// ---------------- epilogue: centroids + masks + tail ------------------------
__global__ void epilogue_kernel(float* __restrict__ out, int extra) {
    int i = blockIdx.x * 256 + threadIdx.x;
    if (i >= extra) return;
    const int T0 = GG * 768;
    float v;
    if (i < GG * 4) {
        const float4 c = g_cent[i >> 2];
        int comp = i & 3;
        v = (comp == 0) ? c.x : (comp == 1) ? c.y : (comp == 2) ? c.z : c.w;
    } else if (i < GG * 4 + GG) {
        v = 1.0f;
    } else {
        v = 0.0f;
    }
    out[T0 + i] = v;
}

// ---------------- host launcher ---------------------------------------------
template<typename T> static T* sym(const void* s) { void* p = nullptr; cudaGetSymbolAddress(&p, s); return (T*)p; }

extern "C" void kernel_launch(void* const* d_in, const int* in_sizes, int n_in,
                              void* d_out, int out_size) {
    const float* coords = (const float*)d_in[0];
    const float* feats  = (const float*)d_in[1];
    const float* W1 = (const float*)d_in[2];
    const float* b1 = (const float*)d_in[3];
    const float* W2 = (const float*)d_in[4];
    const float* b2 = (const float*)d_in[5];
    const float* W3 = (const float*)d_in[6];
    const float* b3 = (const float*)d_in[7];
    const float* W4 = (const float*)d_in[8];
    const float* b4 = (const float*)d_in[9];
    const float* Wa1 = (const float*)d_in[10];
    const float* ba1 = (const float*)d_in[11];
    const float* Wa2 = (const float*)d_in[12];
    const float* ba2 = (const float*)d_in[13];
    float* out = (float*)d_out;

    hf *h1 = sym<hf>(g_h1), *h2 = sym<hf>(g_h2), *h3 = sym<hf>(g_h3);
    hf *pl = sym<hf>(g_pl), *t1 = sym<hf>(g_t1);
    hf *w2h = sym<hf>(g_w2h), *w2l = sym<hf>(g_w2l);
    hf *w3h = sym<hf>(g_w3h), *w3l = sym<hf>(g_w3l);
    hf *w4h = sym<hf>(g_w4h), *w4l = sym<hf>(g_w4l);
    hf *wa1h = sym<hf>(g_wa1h), *wa1l = sym<hf>(g_wa1l);
    hf *wa2h = sym<hf>(g_wa2h), *wa2l = sym<hf>(g_wa2l);

    // opt-in smem (idempotent; host-side, legal during capture)
    cudaFuncSetAttribute(gemm_kernel<true, false, true, false>,
                         cudaFuncAttributeMaxDynamicSharedMemorySize, DSMEM);
    cudaFuncSetAttribute(gemm_kernel<false, false, false, true>,
                         cudaFuncAttributeMaxDynamicSharedMemorySize, DSMEM);
    cudaFuncSetAttribute(gemm_kernel<false, true, false, false>,
                         cudaFuncAttributeMaxDynamicSharedMemorySize, DSMEM);

    // my launches 1-3 (harness injects 2 -> global 3-5); #4 = gemm1 = global #6 (ncu -s 5)
    fps_kernel<<<BB, 1024>>>(coords);
    knn_kernel<<<GG / 2, 256>>>();
    mid_kernel<<<L1_BLOCKS + CW_BLOCKS, 256>>>(feats, W1, b1, W2, W3, W4, Wa1, Wa2);

    // gemm1: h2 = relu(h1 @ W2 + b2): [32768,256] x [256,512]
    gemm_kernel<true, false, true, false><<<dim3(512 / 128, RR / 128), 256, DSMEM>>>(
        h1, w2h, w2l, b2, nullptr, h2, 256, 512);
    // gemm2: h3 = relu(h2 @ W3 + b3): [32768,512] x [512,768]
    gemm_kernel<true, false, true, false><<<dim3(768 / 128, RR / 128), 256, DSMEM>>>(
        h2, w3h, w3l, b3, nullptr, h3, 512, 768);
    // gemm3: pooled = maxpool16(h3 @ W4 + b4): [32768,768] x [768,768] -> [2048,768] fp16
    gemm_kernel<false, false, false, true><<<dim3(768 / 128, RR / 128), 256, DSMEM>>>(
        h3, w4h, w4l, b4, nullptr, nullptr, 768, 768);

    // t1 = relu(pool @ Wa1 + ba1): [2048,768] x [768,768]
    gemm_kernel<true, false, true, false><<<dim3(768 / 128, GG / 128), 256, DSMEM>>>(
        pl, wa1h, wa1l, ba1, nullptr, t1, 768, 768);
    // tokens = t1 @ Wa2 + ba2 -> d_out fp32
    gemm_kernel<false, true, false, false><<<dim3(768 / 128, GG / 128), 256, DSMEM>>>(
        t1, wa2h, wa2l, ba2, out, nullptr, 768, 768);

    int extra = out_size - GG * 768;
    if (extra > 0) {
        epilogue_kernel<<<(extra + 255) / 256, 256>>>(out, extra);
    }
}